// round 2
// baseline (speedup 1.0000x reference)
#include <cuda_runtime.h>
#include <math.h>

#define N_NODES 100000
#define N_NNZ   1000000
#define F_IN    1433
#define F_HID   128
#define F_OUT   64
#define N_POS   20000
#define N_EDGES 40000

// ---------------- scratch (static device globals; no allocation) -------------
__device__ float g_support[(size_t)N_NODES * F_HID];
__device__ float g_y[(size_t)N_NODES * F_HID];
__device__ float g_x[(size_t)N_NODES * F_HID];
__device__ float g_colsum[F_HID];

// ---------------- zero fill --------------------------------------------------
__global__ void zero_kernel(float* __restrict__ a, long n,
                            float* __restrict__ c, int nc) {
    long i = (long)blockIdx.x * blockDim.x + threadIdx.x;
    long stride = (long)gridDim.x * blockDim.x;
    for (; i < n; i += stride) a[i] = 0.0f;
    int t = blockIdx.x * blockDim.x + threadIdx.x;
    if (t < nc) c[t] = 0.0f;
}

// ---------------- tiled SGEMM: C[N,M] = A[N,K] * B[K,M] ----------------------
#define BM 128
#define BN 64
#define BK 16
#define TM 8
#define TN 4

__global__ __launch_bounds__(256)
void sgemm_kernel(const float* __restrict__ A, const float* __restrict__ B,
                  float* __restrict__ C, int N, int K, int M) {
    __shared__ float As[BK][BM + 1];   // +1 pad: conflict-free transposed store
    __shared__ float Bs[BK][BN];

    const int tid = threadIdx.x;              // 256 threads
    const int tx = tid % (BN / TN);           // 16
    const int ty = tid / (BN / TN);           // 16
    const int rowBase = blockIdx.y * BM;
    const int colBase = blockIdx.x * BN;

    float acc[TM][TN];
#pragma unroll
    for (int i = 0; i < TM; i++)
#pragma unroll
        for (int j = 0; j < TN; j++) acc[i][j] = 0.0f;

    for (int k0 = 0; k0 < K; k0 += BK) {
        // load A tile (BM x BK), 8 elems/thread, coalesced along K
#pragma unroll
        for (int it = 0; it < (BM * BK) / 256; it++) {
            int idx = tid + it * 256;
            int r  = idx / BK;
            int kk = idx % BK;
            int gr = rowBase + r, gk = k0 + kk;
            As[kk][r] = (gr < N && gk < K) ? A[(long)gr * K + gk] : 0.0f;
        }
        // load B tile (BK x BN), coalesced along M
#pragma unroll
        for (int it = 0; it < (BK * BN) / 256; it++) {
            int idx = tid + it * 256;
            int kk = idx / BN;
            int c  = idx % BN;
            int gk = k0 + kk, gc = colBase + c;
            Bs[kk][c] = (gk < K && gc < M) ? B[(long)gk * M + gc] : 0.0f;
        }
        __syncthreads();

#pragma unroll
        for (int k = 0; k < BK; k++) {
            float a[TM];
#pragma unroll
            for (int i = 0; i < TM; i++) a[i] = As[k][ty * TM + i];
            float4 b4 = *reinterpret_cast<const float4*>(&Bs[k][tx * TN]);
            float b[TN] = {b4.x, b4.y, b4.z, b4.w};
#pragma unroll
            for (int i = 0; i < TM; i++)
#pragma unroll
                for (int j = 0; j < TN; j++)
                    acc[i][j] = fmaf(a[i], b[j], acc[i][j]);
        }
        __syncthreads();
    }

#pragma unroll
    for (int i = 0; i < TM; i++) {
        int gr = rowBase + ty * TM + i;
        if (gr >= N) continue;
#pragma unroll
        for (int j = 0; j < TN; j++) {
            int gc = colBase + tx * TN + j;
            if (gc < M) C[(long)gr * M + gc] = acc[i][j];
        }
    }
}

// ---------------- SpMM: Y[r] += val * X[c]  (warp per nnz, atomics) ----------
__global__ __launch_bounds__(256)
void spmm_kernel(const int* __restrict__ row, const int* __restrict__ col,
                 const float* __restrict__ val, const float* __restrict__ X,
                 float* __restrict__ Y, int F) {
    int warp = (blockIdx.x * blockDim.x + threadIdx.x) >> 5;
    int lane = threadIdx.x & 31;
    if (warp >= N_NNZ) return;
    int r = row[warp];
    int c = col[warp];
    float v = val[warp];
    const float* xs = X + (long)c * F;
    float* yd = Y + (long)r * F;
    for (int f = lane * 4; f < F; f += 128) {
        float4 x4 = *reinterpret_cast<const float4*>(xs + f);
        atomicAdd(yd + f + 0, v * x4.x);
        atomicAdd(yd + f + 1, v * x4.y);
        atomicAdd(yd + f + 2, v * x4.z);
        atomicAdd(yd + f + 3, v * x4.w);
    }
}

// ---------------- bias + relu + column partial sums --------------------------
// blockDim.x == F (128 or 64); each block handles 64 rows; one atomic per
// (block, column) — avoids serialized single-address atomic storm.
__global__ void bias_relu_colsum_kernel(const float* __restrict__ Y,
                                        const float* __restrict__ b,
                                        float* __restrict__ X,
                                        float* __restrict__ colsum,
                                        int N, int F) {
    int f = threadIdx.x;
    int r0 = blockIdx.x * 64;
    float bias = b[f];
    float s = 0.0f;
    int rEnd = min(r0 + 64, N);
    for (int r = r0; r < rEnd; r++) {
        float v = Y[(long)r * F + f] + bias;
        v = fmaxf(v, 0.0f);
        X[(long)r * F + f] = v;
        s += v;
    }
    atomicAdd(&colsum[f], s);
}

// ---------------- PairNorm (PN-SI): center columns, L2-normalize rows --------
template <int PER>   // PER = F/32
__global__ __launch_bounds__(256)
void pairnorm_kernel(float* __restrict__ X, const float* __restrict__ colsum,
                     int N, int F) {
    int warp = (blockIdx.x * blockDim.x + threadIdx.x) >> 5;
    int lane = threadIdx.x & 31;
    if (warp >= N) return;
    float* xr = X + (long)warp * F;
    const float inv_n = 1.0f / (float)N_NODES;
    float vals[PER];
    float sumsq = 0.0f;
#pragma unroll
    for (int j = 0; j < PER; j++) {
        int f = lane + j * 32;
        float m = colsum[f] * inv_n;
        float v = xr[f] - m;
        vals[j] = v;
        sumsq = fmaf(v, v, sumsq);
    }
#pragma unroll
    for (int o = 16; o > 0; o >>= 1)
        sumsq += __shfl_xor_sync(0xffffffffu, sumsq, o);
    float inv = rsqrtf(1e-6f + sumsq);
#pragma unroll
    for (int j = 0; j < PER; j++)
        xr[lane + j * 32] = vals[j] * inv;
}

// ---------------- decode: per-edge dot product + sigmoid ---------------------
__global__ __launch_bounds__(128)
void decode_kernel(const float* __restrict__ X, const int* __restrict__ pos,
                   const int* __restrict__ neg, float* __restrict__ out) {
    int warp = (blockIdx.x * blockDim.x + threadIdx.x) >> 5;
    int lane = threadIdx.x & 31;
    if (warp >= N_EDGES) return;
    const int* e = (warp < N_POS) ? (pos + 2 * warp) : (neg + 2 * (warp - N_POS));
    int a = e[0];
    int bnode = e[1];
    const float* xa = X + (long)a * F_OUT;
    const float* xb = X + (long)bnode * F_OUT;
    float s = xa[lane] * xb[lane] + xa[lane + 32] * xb[lane + 32];
#pragma unroll
    for (int o = 16; o > 0; o >>= 1)
        s += __shfl_xor_sync(0xffffffffu, s, o);
    if (lane == 0) out[warp] = 1.0f / (1.0f + expf(-s));
}

// ---------------- host orchestration -----------------------------------------
static void run_layer(const float* x_in, int K, const float* W, const float* b,
                      int M, float* support, float* y, float* x_out,
                      float* colsum,
                      const int* adj_row, const int* adj_col, const float* adj_val) {
    // support = x_in @ W
    dim3 gGemm((M + BN - 1) / BN, (N_NODES + BM - 1) / BM);
    sgemm_kernel<<<gGemm, 256>>>(x_in, W, support, N_NODES, K, M);

    // y = 0; colsum = 0
    zero_kernel<<<2048, 256>>>(y, (long)N_NODES * M, colsum, M);

    // y += spmm(adj, support)
    int spmmBlocks = (N_NNZ * 32 + 255) / 256;
    spmm_kernel<<<spmmBlocks, 256>>>(adj_row, adj_col, adj_val, support, y, M);

    // x_out = relu(y + b); colsum += column sums
    bias_relu_colsum_kernel<<<(N_NODES + 63) / 64, M>>>(y, b, x_out, colsum,
                                                        N_NODES, M);

    // pairnorm in place
    int pnBlocks = (N_NODES * 32 + 255) / 256;
    if (M == 128)
        pairnorm_kernel<4><<<pnBlocks, 256>>>(x_out, colsum, N_NODES, M);
    else
        pairnorm_kernel<2><<<pnBlocks, 256>>>(x_out, colsum, N_NODES, M);
}

extern "C" void kernel_launch(void* const* d_in, const int* in_sizes, int n_in,
                              void* d_out, int out_size) {
    const float* in_feature = (const float*)d_in[0];
    const int*   adj_row    = (const int*)d_in[1];
    const int*   adj_col    = (const int*)d_in[2];
    const float* adj_val    = (const float*)d_in[3];
    const int*   pos_edge   = (const int*)d_in[4];
    const int*   neg_edge   = (const int*)d_in[5];
    const float* W0 = (const float*)d_in[6];
    const float* b0 = (const float*)d_in[7];
    const float* W1 = (const float*)d_in[8];
    const float* b1 = (const float*)d_in[9];
    const float* W2 = (const float*)d_in[10];
    const float* b2 = (const float*)d_in[11];
    float* out = (float*)d_out;

    float *support, *y, *x, *colsum;
    cudaGetSymbolAddress((void**)&support, g_support);
    cudaGetSymbolAddress((void**)&y,       g_y);
    cudaGetSymbolAddress((void**)&x,       g_x);
    cudaGetSymbolAddress((void**)&colsum,  g_colsum);

    // layer 0: in_feature [N,1433] -> x [N,128]
    run_layer(in_feature, F_IN, W0, b0, F_HID, support, y, x, colsum,
              adj_row, adj_col, adj_val);
    // layer 1: x [N,128] -> x [N,128]
    run_layer(x, F_HID, W1, b1, F_HID, support, y, x, colsum,
              adj_row, adj_col, adj_val);
    // layer 2: x [N,128] -> x [N,64]
    run_layer(x, F_HID, W2, b2, F_OUT, support, y, x, colsum,
              adj_row, adj_col, adj_val);

    // decode 40000 edges
    decode_kernel<<<(N_EDGES * 32 + 127) / 128, 128>>>(x, pos_edge, neg_edge, out);
}

// round 4
// speedup vs baseline: 1.2614x; 1.2614x over previous
#include <cuda_runtime.h>
#include <math.h>
#include <stdint.h>

#define N_NODES 100000
#define N_NNZ   1000000
#define F_IN    1433
#define F_HID   128
#define F_OUT   64
#define N_POS   20000
#define N_EDGES 40000

// ---------------- scratch (static device globals; no allocation) -------------
__device__ float g_support[(size_t)N_NODES * F_HID];
__device__ float g_y[(size_t)N_NODES * F_HID];
__device__ float g_x[(size_t)N_NODES * F_HID];
__device__ float g_colsum[F_HID];

// ---------------- zero fill --------------------------------------------------
__global__ void zero_kernel(float* __restrict__ a, long n,
                            float* __restrict__ c, int nc) {
    long i = (long)blockIdx.x * blockDim.x + threadIdx.x;
    long stride = (long)gridDim.x * blockDim.x;
    for (; i < n; i += stride) a[i] = 0.0f;
    int t = blockIdx.x * blockDim.x + threadIdx.x;
    if (t < nc) c[t] = 0.0f;
}

// ---------------- TF32 tensor-core GEMM (3xTF32 split, near-fp32 accuracy) ---
// C[N,M] = A[N,K] @ B[K,M], all row-major fp32.
// Block tile 128 x BN_T, BK=16, 8 warps in 4(row) x 2(col) grid,
// warp tile 32 x (BN_T/2), mma.sync.m16n8k8.tf32.

__device__ __forceinline__ uint32_t f2tf32(float x) {
    uint32_t r;
    asm("cvt.rna.tf32.f32 %0, %1;" : "=r"(r) : "f"(x));
    return r;
}

#define MMA_TF32(d, A0, A1, A2, A3, B0, B1)                                     \
    asm volatile(                                                               \
        "mma.sync.aligned.m16n8k8.row.col.f32.tf32.tf32.f32 "                   \
        "{%0,%1,%2,%3}, {%4,%5,%6,%7}, {%8,%9}, {%0,%1,%2,%3};"                 \
        : "+f"((d)[0]), "+f"((d)[1]), "+f"((d)[2]), "+f"((d)[3])                \
        : "r"(A0), "r"(A1), "r"(A2), "r"(A3), "r"(B0), "r"(B1));

template <int BN_T>
__global__ __launch_bounds__(256, 1)
void tf32_gemm_kernel(const float* __restrict__ A, const float* __restrict__ B,
                      float* __restrict__ C, int N, int K, int M) {
    constexpr int NI = BN_T / 16;          // n-subtiles (8 cols) per warp
    __shared__ float As[16][128 + 4];
    __shared__ float Bs[16][BN_T + 4];

    const int tid  = threadIdx.x;
    const int wid  = tid >> 5;
    const int lane = tid & 31;
    const int g    = lane >> 2;            // 0..7
    const int tg   = lane & 3;             // 0..3
    const int wr   = (wid & 3) * 32;       // warp row offset in tile
    const int wc   = (wid >> 2) * (BN_T / 2);
    const int rowBase = blockIdx.y * 128;
    const int colBase = blockIdx.x * BN_T;

    float acc[2][NI][4];
#pragma unroll
    for (int mi = 0; mi < 2; mi++)
#pragma unroll
        for (int ni = 0; ni < NI; ni++)
#pragma unroll
            for (int r = 0; r < 4; r++) acc[mi][ni][r] = 0.0f;

    // A-load assignment: thread -> (row, 8 consecutive k)
    const int ar = tid >> 1;               // 0..127
    const int ak = (tid & 1) * 8;
    const bool arOK = (rowBase + ar) < N;
    const float* Arow = A + (size_t)(rowBase + ar) * K;

    for (int k0 = 0; k0 < K; k0 += 16) {
        // ---- load A tile (128x16), scalar (K may be odd -> no float4) ----
#pragma unroll
        for (int j = 0; j < 8; j++) {
            int gk = k0 + ak + j;
            As[ak + j][ar] = (arOK && gk < K) ? Arow[gk] : 0.0f;
        }
        // ---- load B tile (16 x BN_T), float4 coalesced ----
#pragma unroll
        for (int j = 0; j < BN_T / 64; j++) {
            int id   = tid + j * 256;
            int brow = id / (BN_T / 4);
            int bc4  = id % (BN_T / 4);
            int gk   = k0 + brow;
            float4 v = make_float4(0.f, 0.f, 0.f, 0.f);
            if (gk < K)
                v = *reinterpret_cast<const float4*>(
                        B + (size_t)gk * M + colBase + bc4 * 4);
            Bs[brow][bc4 * 4 + 0] = v.x;
            Bs[brow][bc4 * 4 + 1] = v.y;
            Bs[brow][bc4 * 4 + 2] = v.z;
            Bs[brow][bc4 * 4 + 3] = v.w;
        }
        __syncthreads();

#pragma unroll
        for (int ks = 0; ks < 16; ks += 8) {
            // A fragments (hi/lo) for both 16-row subtiles
            uint32_t ahi[2][4], alo[2][4];
#pragma unroll
            for (int mi = 0; mi < 2; mi++) {
                int r0 = wr + mi * 16 + g;
                float av[4];
                av[0] = As[ks + tg][r0];
                av[1] = As[ks + tg][r0 + 8];
                av[2] = As[ks + tg + 4][r0];
                av[3] = As[ks + tg + 4][r0 + 8];
#pragma unroll
                for (int r = 0; r < 4; r++) {
                    uint32_t h = f2tf32(av[r]);
                    ahi[mi][r] = h;
                    alo[mi][r] = f2tf32(av[r] - __uint_as_float(h));
                }
            }
#pragma unroll
            for (int ni = 0; ni < NI; ni++) {
                int cb = wc + ni * 8 + g;
                float b0 = Bs[ks + tg][cb];
                float b1 = Bs[ks + tg + 4][cb];
                uint32_t bh0 = f2tf32(b0);
                uint32_t bh1 = f2tf32(b1);
                uint32_t bl0 = f2tf32(b0 - __uint_as_float(bh0));
                uint32_t bl1 = f2tf32(b1 - __uint_as_float(bh1));
#pragma unroll
                for (int mi = 0; mi < 2; mi++) {
                    MMA_TF32(acc[mi][ni], ahi[mi][0], ahi[mi][1], ahi[mi][2],
                             ahi[mi][3], bh0, bh1);
                    MMA_TF32(acc[mi][ni], alo[mi][0], alo[mi][1], alo[mi][2],
                             alo[mi][3], bh0, bh1);
                    MMA_TF32(acc[mi][ni], ahi[mi][0], ahi[mi][1], ahi[mi][2],
                             ahi[mi][3], bl0, bl1);
                }
            }
        }
        __syncthreads();
    }

    // ---- store C (float2 per fragment row-half) ----
#pragma unroll
    for (int mi = 0; mi < 2; mi++) {
#pragma unroll
        for (int ni = 0; ni < NI; ni++) {
            int col = colBase + wc + ni * 8 + tg * 2;
            int r0  = rowBase + wr + mi * 16 + g;
            if (r0 < N) {
                float2 v = make_float2(acc[mi][ni][0], acc[mi][ni][1]);
                *reinterpret_cast<float2*>(C + (size_t)r0 * M + col) = v;
            }
            if (r0 + 8 < N) {
                float2 v = make_float2(acc[mi][ni][2], acc[mi][ni][3]);
                *reinterpret_cast<float2*>(C + (size_t)(r0 + 8) * M + col) = v;
            }
        }
    }
}

// ---------------- SpMM: Y[r] += val * X[c]  (warp per nnz, v4 reductions) ----
__global__ __launch_bounds__(256)
void spmm_kernel(const int* __restrict__ row, const int* __restrict__ col,
                 const float* __restrict__ val, const float* __restrict__ X,
                 float* __restrict__ Y, int F) {
    int warp = (blockIdx.x * blockDim.x + threadIdx.x) >> 5;
    int lane = threadIdx.x & 31;
    if (warp >= N_NNZ) return;
    int r = row[warp];
    int c = col[warp];
    float v = val[warp];
    const float* xs = X + (long)c * F;
    float* yd = Y + (long)r * F;
    for (int f = lane * 4; f < F; f += 128) {
        float4 x4 = *reinterpret_cast<const float4*>(xs + f);
        float p0 = v * x4.x, p1 = v * x4.y, p2 = v * x4.z, p3 = v * x4.w;
        asm volatile("red.global.add.v4.f32 [%0], {%1,%2,%3,%4};"
                     :: "l"(yd + f), "f"(p0), "f"(p1), "f"(p2), "f"(p3)
                     : "memory");
    }
}

// ---------------- bias + relu + column partial sums --------------------------
__global__ void bias_relu_colsum_kernel(const float* __restrict__ Y,
                                        const float* __restrict__ b,
                                        float* __restrict__ X,
                                        float* __restrict__ colsum,
                                        int N, int F) {
    int f = threadIdx.x;
    int r0 = blockIdx.x * 64;
    float bias = b[f];
    float s = 0.0f;
    int rEnd = min(r0 + 64, N);
    for (int r = r0; r < rEnd; r++) {
        float v = Y[(long)r * F + f] + bias;
        v = fmaxf(v, 0.0f);
        X[(long)r * F + f] = v;
        s += v;
    }
    atomicAdd(&colsum[f], s);
}

// ---------------- PairNorm (PN-SI): center columns, L2-normalize rows --------
template <int PER>   // PER = F/32
__global__ __launch_bounds__(256)
void pairnorm_kernel(float* __restrict__ X, const float* __restrict__ colsum,
                     int N, int F) {
    int warp = (blockIdx.x * blockDim.x + threadIdx.x) >> 5;
    int lane = threadIdx.x & 31;
    if (warp >= N) return;
    float* xr = X + (long)warp * F;
    const float inv_n = 1.0f / (float)N_NODES;
    float vals[PER];
    float sumsq = 0.0f;
#pragma unroll
    for (int j = 0; j < PER; j++) {
        int f = lane + j * 32;
        float m = colsum[f] * inv_n;
        float v = xr[f] - m;
        vals[j] = v;
        sumsq = fmaf(v, v, sumsq);
    }
#pragma unroll
    for (int o = 16; o > 0; o >>= 1)
        sumsq += __shfl_xor_sync(0xffffffffu, sumsq, o);
    float inv = rsqrtf(1e-6f + sumsq);
#pragma unroll
    for (int j = 0; j < PER; j++)
        xr[lane + j * 32] = vals[j] * inv;
}

// ---------------- decode: per-edge dot product + sigmoid ---------------------
__global__ __launch_bounds__(128)
void decode_kernel(const float* __restrict__ X, const int* __restrict__ pos,
                   const int* __restrict__ neg, float* __restrict__ out) {
    int warp = (blockIdx.x * blockDim.x + threadIdx.x) >> 5;
    int lane = threadIdx.x & 31;
    if (warp >= N_EDGES) return;
    const int* e = (warp < N_POS) ? (pos + 2 * warp) : (neg + 2 * (warp - N_POS));
    int a = e[0];
    int bnode = e[1];
    const float* xa = X + (long)a * F_OUT;
    const float* xb = X + (long)bnode * F_OUT;
    float s = xa[lane] * xb[lane] + xa[lane + 32] * xb[lane + 32];
#pragma unroll
    for (int o = 16; o > 0; o >>= 1)
        s += __shfl_xor_sync(0xffffffffu, s, o);
    if (lane == 0) out[warp] = 1.0f / (1.0f + expf(-s));
}

// ---------------- host orchestration -----------------------------------------
static void run_layer(const float* x_in, int K, const float* W, const float* b,
                      int M, float* support, float* y, float* x_out,
                      float* colsum,
                      const int* adj_row, const int* adj_col, const float* adj_val) {
    // support = x_in @ W  (tensor cores, 3xTF32)
    dim3 gGemm(M / (M == 128 ? 128 : 64), (N_NODES + 127) / 128);
    if (M == 128)
        tf32_gemm_kernel<128><<<gGemm, 256>>>(x_in, W, support, N_NODES, K, M);
    else
        tf32_gemm_kernel<64><<<gGemm, 256>>>(x_in, W, support, N_NODES, K, M);

    // y = 0; colsum = 0
    zero_kernel<<<2048, 256>>>(y, (long)N_NODES * M, colsum, M);

    // y += spmm(adj, support)
    int spmmBlocks = (N_NNZ * 32 + 255) / 256;
    spmm_kernel<<<spmmBlocks, 256>>>(adj_row, adj_col, adj_val, support, y, M);

    // x_out = relu(y + b); colsum += column sums
    bias_relu_colsum_kernel<<<(N_NODES + 63) / 64, M>>>(y, b, x_out, colsum,
                                                        N_NODES, M);

    // pairnorm in place
    int pnBlocks = (N_NODES * 32 + 255) / 256;
    if (M == 128)
        pairnorm_kernel<4><<<pnBlocks, 256>>>(x_out, colsum, N_NODES, M);
    else
        pairnorm_kernel<2><<<pnBlocks, 256>>>(x_out, colsum, N_NODES, M);
}

extern "C" void kernel_launch(void* const* d_in, const int* in_sizes, int n_in,
                              void* d_out, int out_size) {
    const float* in_feature = (const float*)d_in[0];
    const int*   adj_row    = (const int*)d_in[1];
    const int*   adj_col    = (const int*)d_in[2];
    const float* adj_val    = (const float*)d_in[3];
    const int*   pos_edge   = (const int*)d_in[4];
    const int*   neg_edge   = (const int*)d_in[5];
    const float* W0 = (const float*)d_in[6];
    const float* b0 = (const float*)d_in[7];
    const float* W1 = (const float*)d_in[8];
    const float* b1 = (const float*)d_in[9];
    const float* W2 = (const float*)d_in[10];
    const float* b2 = (const float*)d_in[11];
    float* out = (float*)d_out;

    float *support, *y, *x, *colsum;
    cudaGetSymbolAddress((void**)&support, g_support);
    cudaGetSymbolAddress((void**)&y,       g_y);
    cudaGetSymbolAddress((void**)&x,       g_x);
    cudaGetSymbolAddress((void**)&colsum,  g_colsum);

    // layer 0: in_feature [N,1433] -> x [N,128]
    run_layer(in_feature, F_IN, W0, b0, F_HID, support, y, x, colsum,
              adj_row, adj_col, adj_val);
    // layer 1: x [N,128] -> x [N,128]
    run_layer(x, F_HID, W1, b1, F_HID, support, y, x, colsum,
              adj_row, adj_col, adj_val);
    // layer 2: x [N,128] -> x [N,64]
    run_layer(x, F_HID, W2, b2, F_OUT, support, y, x, colsum,
              adj_row, adj_col, adj_val);

    // decode 40000 edges
    decode_kernel<<<(N_EDGES * 32 + 127) / 128, 128>>>(x, pos_edge, neg_edge, out);
}

// round 6
// speedup vs baseline: 1.5669x; 1.2422x over previous
#include <cuda_runtime.h>
#include <cuda_bf16.h>
#include <math.h>
#include <stdint.h>

#define N_NODES 100000
#define N_NNZ   1000000
#define F_IN    1433
#define F_HID   128
#define F_OUT   64
#define N_POS   20000
#define N_EDGES 40000

// ---------------- scratch (static device globals; no allocation) -------------
__device__ float g_support[(size_t)N_NODES * F_HID];
__device__ float g_y[(size_t)N_NODES * F_HID];
__device__ float g_x[(size_t)N_NODES * F_HID];
__device__ float g_colsum[F_HID];

// ---------------- zero fill --------------------------------------------------
__global__ void zero_kernel(float* __restrict__ a, long n,
                            float* __restrict__ c, int nc) {
    long i = (long)blockIdx.x * blockDim.x + threadIdx.x;
    long stride = (long)gridDim.x * blockDim.x;
    for (; i < n; i += stride) a[i] = 0.0f;
    int t = blockIdx.x * blockDim.x + threadIdx.x;
    if (t < nc) c[t] = 0.0f;
}

// ---------------- bf16x3 tensor-core GEMM ------------------------------------
// C[N,M] = A[N,K] @ B[K,M] row-major fp32, near-fp32 accuracy via
// a = hi + lo (bf16 each); C ≈ hi*hi + lo*hi + hi*lo.
// Block tile 128 x BN_T, BK=16, 8 warps (4 row x 2 col), warp tile 32 x BN_T/2.
// mma.sync.m16n8k16.row.col.f32.bf16.bf16.f32, hi/lo pre-packed in SMEM.

// pack two fp32 -> bf16x2 (f_lo -> bits[15:0], f_up -> bits[31:16])
__device__ __forceinline__ uint32_t pack_bf16x2(float f_up, float f_lo) {
    uint32_t r;
    asm("cvt.rn.bf16x2.f32 %0, %1, %2;" : "=r"(r) : "f"(f_up), "f"(f_lo));
    return r;
}

#define MMA_BF16(d, A0, A1, A2, A3, B0, B1)                                     \
    asm volatile(                                                               \
        "mma.sync.aligned.m16n8k16.row.col.f32.bf16.bf16.f32 "                  \
        "{%0,%1,%2,%3}, {%4,%5,%6,%7}, {%8,%9}, {%0,%1,%2,%3};"                 \
        : "+f"((d)[0]), "+f"((d)[1]), "+f"((d)[2]), "+f"((d)[3])                \
        : "r"(A0), "r"(A1), "r"(A2), "r"(A3), "r"(B0), "r"(B1));

template <int BN_T>
__global__ __launch_bounds__(256)
void bf16x3_gemm_kernel(const float* __restrict__ A, const float* __restrict__ B,
                        float* __restrict__ C, int N, int K, int M) {
    constexpr int NI = BN_T / 16;        // 8-col subtiles per warp
    constexpr int SA = 136;              // stride ≡ 8 (mod 32): conflict-free
    constexpr int SB = BN_T + 8;         // 136 or 72, both ≡ 8 (mod 32)
    constexpr int BIDS = 8 * (BN_T / 4); // B-loader thread slots

    __shared__ uint32_t As_hi[8][SA], As_lo[8][SA];
    __shared__ uint32_t Bs_hi[8][SB], Bs_lo[8][SB];

    const int tid  = threadIdx.x;
    const int wid  = tid >> 5;
    const int lane = tid & 31;
    const int g    = lane >> 2;
    const int tg   = lane & 3;
    const int wr   = (wid & 3) * 32;
    const int wc   = (wid >> 2) * (BN_T / 2);
    const int rowBase = blockIdx.y * 128;
    const int colBase = blockIdx.x * BN_T;

    float acc[2][NI][4];
#pragma unroll
    for (int mi = 0; mi < 2; mi++)
#pragma unroll
        for (int ni = 0; ni < NI; ni++)
#pragma unroll
            for (int r = 0; r < 4; r++) acc[mi][ni][r] = 0.0f;

    // A loader: thread -> (row ar, 8 consecutive k at offset ak)
    const int ar = tid >> 1;
    const int ak = (tid & 1) * 8;
    const int k2a = (tid & 1) * 4;
    const bool arOK = (rowBase + ar) < N;
    const float* Arow = A + (size_t)(rowBase + ar) * K;

    // B loader: thread -> (k-pair k2b, float4 col group c4)
    const bool bActive = tid < BIDS;
    const int k2b = tid / (BN_T / 4);
    const int c4  = tid % (BN_T / 4);

    float  fa[8];
    float4 v0, v1;

    auto load_global = [&](int k0) {
#pragma unroll
        for (int j = 0; j < 8; j++) {
            int gk = k0 + ak + j;
            fa[j] = (arOK && gk < K) ? Arow[gk] : 0.0f;
        }
        if (bActive) {
            int gk0 = k0 + 2 * k2b;
            v0 = (gk0 < K) ? *reinterpret_cast<const float4*>(
                                 B + (size_t)gk0 * M + colBase + c4 * 4)
                           : make_float4(0.f, 0.f, 0.f, 0.f);
            v1 = (gk0 + 1 < K) ? *reinterpret_cast<const float4*>(
                                     B + (size_t)(gk0 + 1) * M + colBase + c4 * 4)
                               : make_float4(0.f, 0.f, 0.f, 0.f);
        }
    };

    auto store_smem = [&]() {
#pragma unroll
        for (int j = 0; j < 4; j++) {
            float f0 = fa[2 * j], f1 = fa[2 * j + 1];
            uint32_t h = pack_bf16x2(f1, f0);
            float h0 = __uint_as_float(h << 16);
            float h1 = __uint_as_float(h & 0xFFFF0000u);
            uint32_t l = pack_bf16x2(f1 - h1, f0 - h0);
            As_hi[k2a + j][ar] = h;
            As_lo[k2a + j][ar] = l;
        }
        if (bActive) {
            const float e0[4] = {v0.x, v0.y, v0.z, v0.w};
            const float e1[4] = {v1.x, v1.y, v1.z, v1.w};
#pragma unroll
            for (int e = 0; e < 4; e++) {
                int col = c4 * 4 + e;
                uint32_t h = pack_bf16x2(e1[e], e0[e]);   // k-pair packed
                float h0 = __uint_as_float(h << 16);
                float h1 = __uint_as_float(h & 0xFFFF0000u);
                uint32_t l = pack_bf16x2(e1[e] - h1, e0[e] - h0);
                Bs_hi[k2b][col] = h;
                Bs_lo[k2b][col] = l;
            }
        }
    };

    const int KT = (K + 15) / 16;
    load_global(0);

    for (int kt = 0; kt < KT; kt++) {
        store_smem();
        __syncthreads();
        if (kt + 1 < KT) load_global((kt + 1) * 16);

        uint32_t ah[2][4], al[2][4];
#pragma unroll
        for (int mi = 0; mi < 2; mi++) {
            int r0 = wr + mi * 16 + g;
            ah[mi][0] = As_hi[tg][r0];
            ah[mi][1] = As_hi[tg][r0 + 8];
            ah[mi][2] = As_hi[tg + 4][r0];
            ah[mi][3] = As_hi[tg + 4][r0 + 8];
            al[mi][0] = As_lo[tg][r0];
            al[mi][1] = As_lo[tg][r0 + 8];
            al[mi][2] = As_lo[tg + 4][r0];
            al[mi][3] = As_lo[tg + 4][r0 + 8];
        }
#pragma unroll
        for (int ni = 0; ni < NI; ni++) {
            int col = wc + ni * 8 + g;
            uint32_t bh0 = Bs_hi[tg][col];
            uint32_t bh1 = Bs_hi[tg + 4][col];
            uint32_t bl0 = Bs_lo[tg][col];
            uint32_t bl1 = Bs_lo[tg + 4][col];
#pragma unroll
            for (int mi = 0; mi < 2; mi++) {
                MMA_BF16(acc[mi][ni], ah[mi][0], ah[mi][1], ah[mi][2], ah[mi][3],
                         bh0, bh1);
                MMA_BF16(acc[mi][ni], al[mi][0], al[mi][1], al[mi][2], al[mi][3],
                         bh0, bh1);
                MMA_BF16(acc[mi][ni], ah[mi][0], ah[mi][1], ah[mi][2], ah[mi][3],
                         bl0, bl1);
            }
        }
        __syncthreads();
    }

    // ---- store C ----
#pragma unroll
    for (int mi = 0; mi < 2; mi++) {
#pragma unroll
        for (int ni = 0; ni < NI; ni++) {
            int col = colBase + wc + ni * 8 + tg * 2;
            int r0  = rowBase + wr + mi * 16 + g;
            if (r0 < N) {
                float2 v = make_float2(acc[mi][ni][0], acc[mi][ni][1]);
                *reinterpret_cast<float2*>(C + (size_t)r0 * M + col) = v;
            }
            if (r0 + 8 < N) {
                float2 v = make_float2(acc[mi][ni][2], acc[mi][ni][3]);
                *reinterpret_cast<float2*>(C + (size_t)(r0 + 8) * M + col) = v;
            }
        }
    }
}

// ---------------- SpMM: Y[r] += val * X[c]  (warp per nnz, v4 reductions) ----
__global__ __launch_bounds__(256)
void spmm_kernel(const int* __restrict__ row, const int* __restrict__ col,
                 const float* __restrict__ val, const float* __restrict__ X,
                 float* __restrict__ Y, int F) {
    int warp = (blockIdx.x * blockDim.x + threadIdx.x) >> 5;
    int lane = threadIdx.x & 31;
    if (warp >= N_NNZ) return;
    int r = row[warp];
    int c = col[warp];
    float v = val[warp];
    const float* xs = X + (long)c * F;
    float* yd = Y + (long)r * F;
    for (int f = lane * 4; f < F; f += 128) {
        float4 x4 = *reinterpret_cast<const float4*>(xs + f);
        float p0 = v * x4.x, p1 = v * x4.y, p2 = v * x4.z, p3 = v * x4.w;
        asm volatile("red.global.add.v4.f32 [%0], {%1,%2,%3,%4};"
                     :: "l"(yd + f), "f"(p0), "f"(p1), "f"(p2), "f"(p3)
                     : "memory");
    }
}

// ---------------- bias + relu + column partial sums --------------------------
__global__ void bias_relu_colsum_kernel(const float* __restrict__ Y,
                                        const float* __restrict__ b,
                                        float* __restrict__ X,
                                        float* __restrict__ colsum,
                                        int N, int F) {
    int f = threadIdx.x;
    int r0 = blockIdx.x * 64;
    float bias = b[f];
    float s = 0.0f;
    int rEnd = min(r0 + 64, N);
    for (int r = r0; r < rEnd; r++) {
        float v = Y[(long)r * F + f] + bias;
        v = fmaxf(v, 0.0f);
        X[(long)r * F + f] = v;
        s += v;
    }
    atomicAdd(&colsum[f], s);
}

// ---------------- PairNorm (PN-SI): center columns, L2-normalize rows --------
template <int PER>   // PER = F/32
__global__ __launch_bounds__(256)
void pairnorm_kernel(float* __restrict__ X, const float* __restrict__ colsum,
                     int N, int F) {
    int warp = (blockIdx.x * blockDim.x + threadIdx.x) >> 5;
    int lane = threadIdx.x & 31;
    if (warp >= N) return;
    float* xr = X + (long)warp * F;
    const float inv_n = 1.0f / (float)N_NODES;
    float vals[PER];
    float sumsq = 0.0f;
#pragma unroll
    for (int j = 0; j < PER; j++) {
        int f = lane + j * 32;
        float m = colsum[f] * inv_n;
        float v = xr[f] - m;
        vals[j] = v;
        sumsq = fmaf(v, v, sumsq);
    }
#pragma unroll
    for (int o = 16; o > 0; o >>= 1)
        sumsq += __shfl_xor_sync(0xffffffffu, sumsq, o);
    float inv = rsqrtf(1e-6f + sumsq);
#pragma unroll
    for (int j = 0; j < PER; j++)
        xr[lane + j * 32] = vals[j] * inv;
}

// ---------------- decode: per-edge dot product + sigmoid ---------------------
__global__ __launch_bounds__(128)
void decode_kernel(const float* __restrict__ X, const int* __restrict__ pos,
                   const int* __restrict__ neg, float* __restrict__ out) {
    int warp = (blockIdx.x * blockDim.x + threadIdx.x) >> 5;
    int lane = threadIdx.x & 31;
    if (warp >= N_EDGES) return;
    const int* e = (warp < N_POS) ? (pos + 2 * warp) : (neg + 2 * (warp - N_POS));
    int a = e[0];
    int bnode = e[1];
    const float* xa = X + (long)a * F_OUT;
    const float* xb = X + (long)bnode * F_OUT;
    float s = xa[lane] * xb[lane] + xa[lane + 32] * xb[lane + 32];
#pragma unroll
    for (int o = 16; o > 0; o >>= 1)
        s += __shfl_xor_sync(0xffffffffu, s, o);
    if (lane == 0) out[warp] = 1.0f / (1.0f + expf(-s));
}

// ---------------- host orchestration -----------------------------------------
static void run_layer(const float* x_in, int K, const float* W, const float* b,
                      int M, float* support, float* y, float* x_out,
                      float* colsum,
                      const int* adj_row, const int* adj_col, const float* adj_val) {
    // support = x_in @ W  (tensor cores, bf16x3)
    dim3 gGemm(1, (N_NODES + 127) / 128);
    if (M == 128)
        bf16x3_gemm_kernel<128><<<gGemm, 256>>>(x_in, W, support, N_NODES, K, M);
    else
        bf16x3_gemm_kernel<64><<<gGemm, 256>>>(x_in, W, support, N_NODES, K, M);

    // y = 0; colsum = 0
    zero_kernel<<<2048, 256>>>(y, (long)N_NODES * M, colsum, M);

    // y += spmm(adj, support)
    int spmmBlocks = (N_NNZ * 32 + 255) / 256;
    spmm_kernel<<<spmmBlocks, 256>>>(adj_row, adj_col, adj_val, support, y, M);

    // x_out = relu(y + b); colsum += column sums
    bias_relu_colsum_kernel<<<(N_NODES + 63) / 64, M>>>(y, b, x_out, colsum,
                                                        N_NODES, M);

    // pairnorm in place
    int pnBlocks = (N_NODES * 32 + 255) / 256;
    if (M == 128)
        pairnorm_kernel<4><<<pnBlocks, 256>>>(x_out, colsum, N_NODES, M);
    else
        pairnorm_kernel<2><<<pnBlocks, 256>>>(x_out, colsum, N_NODES, M);
}

extern "C" void kernel_launch(void* const* d_in, const int* in_sizes, int n_in,
                              void* d_out, int out_size) {
    const float* in_feature = (const float*)d_in[0];
    const int*   adj_row    = (const int*)d_in[1];
    const int*   adj_col    = (const int*)d_in[2];
    const float* adj_val    = (const float*)d_in[3];
    const int*   pos_edge   = (const int*)d_in[4];
    const int*   neg_edge   = (const int*)d_in[5];
    const float* W0 = (const float*)d_in[6];
    const float* b0 = (const float*)d_in[7];
    const float* W1 = (const float*)d_in[8];
    const float* b1 = (const float*)d_in[9];
    const float* W2 = (const float*)d_in[10];
    const float* b2 = (const float*)d_in[11];
    float* out = (float*)d_out;

    float *support, *y, *x, *colsum;
    cudaGetSymbolAddress((void**)&support, g_support);
    cudaGetSymbolAddress((void**)&y,       g_y);
    cudaGetSymbolAddress((void**)&x,       g_x);
    cudaGetSymbolAddress((void**)&colsum,  g_colsum);

    // layer 0: in_feature [N,1433] -> x [N,128]
    run_layer(in_feature, F_IN, W0, b0, F_HID, support, y, x, colsum,
              adj_row, adj_col, adj_val);
    // layer 1: x [N,128] -> x [N,128]
    run_layer(x, F_HID, W1, b1, F_HID, support, y, x, colsum,
              adj_row, adj_col, adj_val);
    // layer 2: x [N,128] -> x [N,64]
    run_layer(x, F_HID, W2, b2, F_OUT, support, y, x, colsum,
              adj_row, adj_col, adj_val);

    // decode 40000 edges
    decode_kernel<<<(N_EDGES * 32 + 127) / 128, 128>>>(x, pos_edge, neg_edge, out);
}

// round 8
// speedup vs baseline: 2.5213x; 1.6091x over previous
#include <cuda_runtime.h>
#include <cuda_bf16.h>
#include <math.h>
#include <stdint.h>

#define N_NODES 100000
#define N_NNZ   1000000
#define F_IN    1433
#define F_HID   128
#define F_OUT   64
#define N_POS   20000
#define N_EDGES 40000

#define SCAN_BS 1024
#define SCAN_NB ((N_NODES + 1 + SCAN_BS - 1) / SCAN_BS)   // 98

// ---------------- scratch (static device globals; no allocation) -------------
__device__ float g_support[(size_t)N_NODES * F_HID];
__device__ float g_x[(size_t)N_NODES * F_HID];
__device__ float g_colsum[F_HID];
__device__ int   g_row_ptr[N_NODES + 1];
__device__ int   g_row_work[N_NODES + 1];
__device__ int   g_csr_col[N_NNZ];
__device__ float g_csr_val[N_NNZ];
__device__ int   g_blocksum[SCAN_NB];

// ================= CSR build ==================================================
__global__ void hist_zero_kernel(int* __restrict__ row_ptr) {
    int i = blockIdx.x * blockDim.x + threadIdx.x;
    if (i <= N_NODES) row_ptr[i] = 0;
}

__global__ void hist_kernel(const int* __restrict__ row, int* __restrict__ row_ptr) {
    int i = blockIdx.x * blockDim.x + threadIdx.x;
    if (i < N_NNZ) atomicAdd(&row_ptr[row[i] + 1], 1);
}

// inclusive scan, stage A: per-block scan + block totals
__global__ __launch_bounds__(SCAN_BS)
void scan_a_kernel(int* __restrict__ data, int* __restrict__ blocksum, int n) {
    __shared__ int sh[SCAN_BS];
    int gid = blockIdx.x * SCAN_BS + threadIdx.x;
    int v = (gid < n) ? data[gid] : 0;
    sh[threadIdx.x] = v;
    __syncthreads();
#pragma unroll
    for (int o = 1; o < SCAN_BS; o <<= 1) {
        int t = (threadIdx.x >= o) ? sh[threadIdx.x - o] : 0;
        __syncthreads();
        sh[threadIdx.x] += t;
        __syncthreads();
    }
    if (gid < n) data[gid] = sh[threadIdx.x];
    if (threadIdx.x == SCAN_BS - 1) blocksum[blockIdx.x] = sh[threadIdx.x];
}

// stage B: single block scans block totals (SCAN_NB <= 1024)
__global__ __launch_bounds__(SCAN_BS)
void scan_b_kernel(int* __restrict__ blocksum, int nb) {
    __shared__ int sh[SCAN_BS];
    int v = (threadIdx.x < nb) ? blocksum[threadIdx.x] : 0;
    sh[threadIdx.x] = v;
    __syncthreads();
#pragma unroll
    for (int o = 1; o < SCAN_BS; o <<= 1) {
        int t = (threadIdx.x >= o) ? sh[threadIdx.x - o] : 0;
        __syncthreads();
        sh[threadIdx.x] += t;
        __syncthreads();
    }
    if (threadIdx.x < nb) blocksum[threadIdx.x] = sh[threadIdx.x];
}

// stage C: add previous-block offsets; also copy to row_work
__global__ __launch_bounds__(SCAN_BS)
void scan_c_kernel(int* __restrict__ data, const int* __restrict__ blocksum,
                   int* __restrict__ work, int n) {
    int gid = blockIdx.x * SCAN_BS + threadIdx.x;
    if (gid >= n) return;
    int v = data[gid];
    if (blockIdx.x > 0) v += blocksum[blockIdx.x - 1];
    data[gid] = v;
    work[gid] = v;
}

__global__ void scatter_kernel(const int* __restrict__ row, const int* __restrict__ col,
                               const float* __restrict__ val,
                               int* __restrict__ work,
                               int* __restrict__ csr_col, float* __restrict__ csr_val) {
    int i = blockIdx.x * blockDim.x + threadIdx.x;
    if (i >= N_NNZ) return;
    int pos = atomicAdd(&work[row[i]], 1);
    csr_col[pos] = col[i];
    csr_val[pos] = val[i];
}

// ================= fused CSR aggregation ======================================
// x_out[r] = relu( sum_nnz val * X[col] + bias ); colsum += column sums.
// 8 warps/block, 4 rows per warp => 32 rows/block. VPL = floats per lane.
template <int F, int VPL>
__global__ __launch_bounds__(256)
void csr_agg_kernel(const int* __restrict__ row_ptr,
                    const int* __restrict__ csr_col,
                    const float* __restrict__ csr_val,
                    const float* __restrict__ X,
                    const float* __restrict__ bias,
                    float* __restrict__ Xout,
                    float* __restrict__ colsum) {
    __shared__ float scol[F];
    const int tid  = threadIdx.x;
    const int wid  = tid >> 5;
    const int lane = tid & 31;

    if (tid < F) scol[tid] = 0.0f;
    __syncthreads();

    float bz[VPL];
#pragma unroll
    for (int j = 0; j < VPL; j++) bz[j] = bias[lane * VPL + j];

    float csum[VPL];
#pragma unroll
    for (int j = 0; j < VPL; j++) csum[j] = 0.0f;

    const int rowBase = blockIdx.x * 32 + wid * 4;

#pragma unroll
    for (int rr = 0; rr < 4; rr++) {
        const int r = rowBase + rr;
        const int start = row_ptr[r];
        const int end   = row_ptr[r + 1];

        float acc[VPL];
#pragma unroll
        for (int j = 0; j < VPL; j++) acc[j] = 0.0f;

        for (int base = start; base < end; base += 32) {
            int idx = base + lane;
            int   cv = 0;
            float vv = 0.0f;
            if (idx < end) { cv = csr_col[idx]; vv = csr_val[idx]; }
            int count = min(32, end - base);
            for (int j = 0; j < count; j++) {
                int   c = __shfl_sync(0xffffffffu, cv, j);
                float v = __shfl_sync(0xffffffffu, vv, j);
                const float* xr = X + (size_t)c * F;
                if (VPL == 4) {
                    float4 x4 = reinterpret_cast<const float4*>(xr)[lane];
                    acc[0] = fmaf(v, x4.x, acc[0]);
                    acc[1] = fmaf(v, x4.y, acc[1]);
                    acc[2] = fmaf(v, x4.z, acc[2]);
                    acc[3] = fmaf(v, x4.w, acc[3]);
                } else {
                    float2 x2 = reinterpret_cast<const float2*>(xr)[lane];
                    acc[0] = fmaf(v, x2.x, acc[0]);
                    acc[1] = fmaf(v, x2.y, acc[1]);
                }
            }
        }

        // bias + relu, store, accumulate colsum
#pragma unroll
        for (int j = 0; j < VPL; j++) {
            float o = fmaxf(acc[j] + bz[j], 0.0f);
            acc[j] = o;
            csum[j] += o;
        }
        float* od = Xout + (size_t)r * F;
        if (VPL == 4) {
            float4 o4 = make_float4(acc[0], acc[1], acc[2], acc[3]);
            reinterpret_cast<float4*>(od)[lane] = o4;
        } else {
            float2 o2 = make_float2(acc[0], acc[1]);
            reinterpret_cast<float2*>(od)[lane] = o2;
        }
    }

#pragma unroll
    for (int j = 0; j < VPL; j++)
        atomicAdd(&scol[lane * VPL + j], csum[j]);
    __syncthreads();
    if (tid < F) atomicAdd(&colsum[tid], scol[tid]);
}

__global__ void zero_colsum_kernel(float* __restrict__ colsum, int F) {
    if (threadIdx.x < F) colsum[threadIdx.x] = 0.0f;
}

// ---------------- bf16x3 tensor-core GEMM ------------------------------------
__device__ __forceinline__ uint32_t pack_bf16x2(float f_up, float f_lo) {
    uint32_t r;
    asm("cvt.rn.bf16x2.f32 %0, %1, %2;" : "=r"(r) : "f"(f_up), "f"(f_lo));
    return r;
}

#define MMA_BF16(d, A0, A1, A2, A3, B0, B1)                                     \
    asm volatile(                                                               \
        "mma.sync.aligned.m16n8k16.row.col.f32.bf16.bf16.f32 "                  \
        "{%0,%1,%2,%3}, {%4,%5,%6,%7}, {%8,%9}, {%0,%1,%2,%3};"                 \
        : "+f"((d)[0]), "+f"((d)[1]), "+f"((d)[2]), "+f"((d)[3])                \
        : "r"(A0), "r"(A1), "r"(A2), "r"(A3), "r"(B0), "r"(B1));

template <int BN_T>
__global__ __launch_bounds__(256)
void bf16x3_gemm_kernel(const float* __restrict__ A, const float* __restrict__ B,
                        float* __restrict__ C, int N, int K, int M) {
    constexpr int NI = BN_T / 16;
    constexpr int SA = 136;
    constexpr int SB = BN_T + 8;
    constexpr int BIDS = 8 * (BN_T / 4);

    __shared__ uint32_t As_hi[8][SA], As_lo[8][SA];
    __shared__ uint32_t Bs_hi[8][SB], Bs_lo[8][SB];

    const int tid  = threadIdx.x;
    const int wid  = tid >> 5;
    const int lane = tid & 31;
    const int g    = lane >> 2;
    const int tg   = lane & 3;
    const int wr   = (wid & 3) * 32;
    const int wc   = (wid >> 2) * (BN_T / 2);
    const int rowBase = blockIdx.y * 128;
    const int colBase = blockIdx.x * BN_T;

    float acc[2][NI][4];
#pragma unroll
    for (int mi = 0; mi < 2; mi++)
#pragma unroll
        for (int ni = 0; ni < NI; ni++)
#pragma unroll
            for (int r = 0; r < 4; r++) acc[mi][ni][r] = 0.0f;

    const int ar = tid >> 1;
    const int ak = (tid & 1) * 8;
    const int k2a = (tid & 1) * 4;
    const bool arOK = (rowBase + ar) < N;
    const float* Arow = A + (size_t)(rowBase + ar) * K;

    const bool bActive = tid < BIDS;
    const int k2b = tid / (BN_T / 4);
    const int c4  = tid % (BN_T / 4);

    float  fa[8];
    float4 v0, v1;

    auto load_global = [&](int k0) {
#pragma unroll
        for (int j = 0; j < 8; j++) {
            int gk = k0 + ak + j;
            fa[j] = (arOK && gk < K) ? Arow[gk] : 0.0f;
        }
        if (bActive) {
            int gk0 = k0 + 2 * k2b;
            v0 = (gk0 < K) ? *reinterpret_cast<const float4*>(
                                 B + (size_t)gk0 * M + colBase + c4 * 4)
                           : make_float4(0.f, 0.f, 0.f, 0.f);
            v1 = (gk0 + 1 < K) ? *reinterpret_cast<const float4*>(
                                     B + (size_t)(gk0 + 1) * M + colBase + c4 * 4)
                               : make_float4(0.f, 0.f, 0.f, 0.f);
        }
    };

    auto store_smem = [&]() {
#pragma unroll
        for (int j = 0; j < 4; j++) {
            float f0 = fa[2 * j], f1 = fa[2 * j + 1];
            uint32_t h = pack_bf16x2(f1, f0);
            float h0 = __uint_as_float(h << 16);
            float h1 = __uint_as_float(h & 0xFFFF0000u);
            uint32_t l = pack_bf16x2(f1 - h1, f0 - h0);
            As_hi[k2a + j][ar] = h;
            As_lo[k2a + j][ar] = l;
        }
        if (bActive) {
            const float e0[4] = {v0.x, v0.y, v0.z, v0.w};
            const float e1[4] = {v1.x, v1.y, v1.z, v1.w};
#pragma unroll
            for (int e = 0; e < 4; e++) {
                int col = c4 * 4 + e;
                uint32_t h = pack_bf16x2(e1[e], e0[e]);
                float h0 = __uint_as_float(h << 16);
                float h1 = __uint_as_float(h & 0xFFFF0000u);
                uint32_t l = pack_bf16x2(e1[e] - h1, e0[e] - h0);
                Bs_hi[k2b][col] = h;
                Bs_lo[k2b][col] = l;
            }
        }
    };

    const int KT = (K + 15) / 16;
    load_global(0);

    for (int kt = 0; kt < KT; kt++) {
        store_smem();
        __syncthreads();
        if (kt + 1 < KT) load_global((kt + 1) * 16);

        uint32_t ah[2][4], al[2][4];
#pragma unroll
        for (int mi = 0; mi < 2; mi++) {
            int r0 = wr + mi * 16 + g;
            ah[mi][0] = As_hi[tg][r0];
            ah[mi][1] = As_hi[tg][r0 + 8];
            ah[mi][2] = As_hi[tg + 4][r0];
            ah[mi][3] = As_hi[tg + 4][r0 + 8];
            al[mi][0] = As_lo[tg][r0];
            al[mi][1] = As_lo[tg][r0 + 8];
            al[mi][2] = As_lo[tg + 4][r0];
            al[mi][3] = As_lo[tg + 4][r0 + 8];
        }
#pragma unroll
        for (int ni = 0; ni < NI; ni++) {
            int col = wc + ni * 8 + g;
            uint32_t bh0 = Bs_hi[tg][col];
            uint32_t bh1 = Bs_hi[tg + 4][col];
            uint32_t bl0 = Bs_lo[tg][col];
            uint32_t bl1 = Bs_lo[tg + 4][col];
#pragma unroll
            for (int mi = 0; mi < 2; mi++) {
                MMA_BF16(acc[mi][ni], ah[mi][0], ah[mi][1], ah[mi][2], ah[mi][3],
                         bh0, bh1);
                MMA_BF16(acc[mi][ni], al[mi][0], al[mi][1], al[mi][2], al[mi][3],
                         bh0, bh1);
                MMA_BF16(acc[mi][ni], ah[mi][0], ah[mi][1], ah[mi][2], ah[mi][3],
                         bl0, bl1);
            }
        }
        __syncthreads();
    }

#pragma unroll
    for (int mi = 0; mi < 2; mi++) {
#pragma unroll
        for (int ni = 0; ni < NI; ni++) {
            int col = colBase + wc + ni * 8 + tg * 2;
            int r0  = rowBase + wr + mi * 16 + g;
            if (r0 < N) {
                float2 v = make_float2(acc[mi][ni][0], acc[mi][ni][1]);
                *reinterpret_cast<float2*>(C + (size_t)r0 * M + col) = v;
            }
            if (r0 + 8 < N) {
                float2 v = make_float2(acc[mi][ni][2], acc[mi][ni][3]);
                *reinterpret_cast<float2*>(C + (size_t)(r0 + 8) * M + col) = v;
            }
        }
    }
}

// ---------------- PairNorm (PN-SI) -------------------------------------------
template <int PER>
__global__ __launch_bounds__(256)
void pairnorm_kernel(float* __restrict__ X, const float* __restrict__ colsum,
                     int N, int F) {
    int warp = (blockIdx.x * blockDim.x + threadIdx.x) >> 5;
    int lane = threadIdx.x & 31;
    if (warp >= N) return;
    float* xr = X + (long)warp * F;
    const float inv_n = 1.0f / (float)N_NODES;
    float vals[PER];
    float sumsq = 0.0f;
#pragma unroll
    for (int j = 0; j < PER; j++) {
        int f = lane + j * 32;
        float m = colsum[f] * inv_n;
        float v = xr[f] - m;
        vals[j] = v;
        sumsq = fmaf(v, v, sumsq);
    }
#pragma unroll
    for (int o = 16; o > 0; o >>= 1)
        sumsq += __shfl_xor_sync(0xffffffffu, sumsq, o);
    float inv = rsqrtf(1e-6f + sumsq);
#pragma unroll
    for (int j = 0; j < PER; j++)
        xr[lane + j * 32] = vals[j] * inv;
}

// ---------------- decode ------------------------------------------------------
__global__ __launch_bounds__(128)
void decode_kernel(const float* __restrict__ X, const int* __restrict__ pos,
                   const int* __restrict__ neg, float* __restrict__ out) {
    int warp = (blockIdx.x * blockDim.x + threadIdx.x) >> 5;
    int lane = threadIdx.x & 31;
    if (warp >= N_EDGES) return;
    const int* e = (warp < N_POS) ? (pos + 2 * warp) : (neg + 2 * (warp - N_POS));
    int a = e[0];
    int bnode = e[1];
    const float* xa = X + (long)a * F_OUT;
    const float* xb = X + (long)bnode * F_OUT;
    float s = xa[lane] * xb[lane] + xa[lane + 32] * xb[lane + 32];
#pragma unroll
    for (int o = 16; o > 0; o >>= 1)
        s += __shfl_xor_sync(0xffffffffu, s, o);
    if (lane == 0) out[warp] = 1.0f / (1.0f + expf(-s));
}

// ---------------- host orchestration -----------------------------------------
static void run_layer(const float* x_in, int K, const float* W, const float* b,
                      int M, float* support, float* x_out, float* colsum,
                      const int* row_ptr, const int* csr_col, const float* csr_val) {
    dim3 gGemm(1, (N_NODES + 127) / 128);
    if (M == 128)
        bf16x3_gemm_kernel<128><<<gGemm, 256>>>(x_in, W, support, N_NODES, K, M);
    else
        bf16x3_gemm_kernel<64><<<gGemm, 256>>>(x_in, W, support, N_NODES, K, M);

    zero_colsum_kernel<<<1, 128>>>(colsum, M);

    // fused spmm + bias + relu + colsum
    int aggBlocks = N_NODES / 32;   // 3125
    if (M == 128)
        csr_agg_kernel<128, 4><<<aggBlocks, 256>>>(row_ptr, csr_col, csr_val,
                                                   support, b, x_out, colsum);
    else
        csr_agg_kernel<64, 2><<<aggBlocks, 256>>>(row_ptr, csr_col, csr_val,
                                                  support, b, x_out, colsum);

    int pnBlocks = (N_NODES * 32 + 255) / 256;
    if (M == 128)
        pairnorm_kernel<4><<<pnBlocks, 256>>>(x_out, colsum, N_NODES, M);
    else
        pairnorm_kernel<2><<<pnBlocks, 256>>>(x_out, colsum, N_NODES, M);
}

extern "C" void kernel_launch(void* const* d_in, const int* in_sizes, int n_in,
                              void* d_out, int out_size) {
    const float* in_feature = (const float*)d_in[0];
    const int*   adj_row    = (const int*)d_in[1];
    const int*   adj_col    = (const int*)d_in[2];
    const float* adj_val    = (const float*)d_in[3];
    const int*   pos_edge   = (const int*)d_in[4];
    const int*   neg_edge   = (const int*)d_in[5];
    const float* W0 = (const float*)d_in[6];
    const float* b0 = (const float*)d_in[7];
    const float* W1 = (const float*)d_in[8];
    const float* b1 = (const float*)d_in[9];
    const float* W2 = (const float*)d_in[10];
    const float* b2 = (const float*)d_in[11];
    float* out = (float*)d_out;

    float *support, *x, *colsum, *csr_val;
    int *row_ptr, *row_work, *csr_col, *blocksum;
    cudaGetSymbolAddress((void**)&support,  g_support);
    cudaGetSymbolAddress((void**)&x,        g_x);
    cudaGetSymbolAddress((void**)&colsum,   g_colsum);
    cudaGetSymbolAddress((void**)&row_ptr,  g_row_ptr);
    cudaGetSymbolAddress((void**)&row_work, g_row_work);
    cudaGetSymbolAddress((void**)&csr_col,  g_csr_col);
    cudaGetSymbolAddress((void**)&csr_val,  g_csr_val);
    cudaGetSymbolAddress((void**)&blocksum, g_blocksum);

    // ---- build CSR (once; reused by all 3 layers) ----
    hist_zero_kernel<<<(N_NODES + 1 + 255) / 256, 256>>>(row_ptr);
    hist_kernel<<<(N_NNZ + 255) / 256, 256>>>(adj_row, row_ptr);
    scan_a_kernel<<<SCAN_NB, SCAN_BS>>>(row_ptr, blocksum, N_NODES + 1);
    scan_b_kernel<<<1, SCAN_BS>>>(blocksum, SCAN_NB);
    scan_c_kernel<<<SCAN_NB, SCAN_BS>>>(row_ptr, blocksum, row_work, N_NODES + 1);
    scatter_kernel<<<(N_NNZ + 255) / 256, 256>>>(adj_row, adj_col, adj_val,
                                                 row_work, csr_col, csr_val);

    // ---- 3 GCN layers ----
    run_layer(in_feature, F_IN, W0, b0, F_HID, support, x, colsum,
              row_ptr, csr_col, csr_val);
    run_layer(x, F_HID, W1, b1, F_HID, support, x, colsum,
              row_ptr, csr_col, csr_val);
    run_layer(x, F_HID, W2, b2, F_OUT, support, x, colsum,
              row_ptr, csr_col, csr_val);

    // ---- decode ----
    decode_kernel<<<(N_EDGES * 32 + 127) / 128, 128>>>(x, pos_edge, neg_edge, out);
}

// round 9
// speedup vs baseline: 2.6580x; 1.0542x over previous
#include <cuda_runtime.h>
#include <cuda_bf16.h>
#include <cuda_fp16.h>
#include <math.h>
#include <stdint.h>

#define N_NODES 100000
#define N_NNZ   1000000
#define F_IN    1433
#define F_HID   128
#define F_OUT   64
#define N_POS   20000
#define N_EDGES 40000

#define SCAN_BS 1024
#define SCAN_NB ((N_NODES + 1 + SCAN_BS - 1) / SCAN_BS)   // 98

// ---------------- scratch (static device globals; no allocation) -------------
__device__ float g_support[(size_t)N_NODES * F_HID];
__device__ float g_x[(size_t)N_NODES * F_HID];
__device__ float g_colsum[F_HID];
__device__ int   g_row_ptr[N_NODES + 1];
__device__ int   g_row_work[N_NODES + 1];
__device__ int   g_csr_col[N_NNZ];
__device__ float g_csr_val[N_NNZ];
__device__ int   g_blocksum[SCAN_NB];

// ================= CSR build ==================================================
__global__ void hist_zero_kernel(int* __restrict__ row_ptr) {
    int i = blockIdx.x * blockDim.x + threadIdx.x;
    if (i <= N_NODES) row_ptr[i] = 0;
}

__global__ void hist_kernel(const int* __restrict__ row, int* __restrict__ row_ptr) {
    int i = blockIdx.x * blockDim.x + threadIdx.x;
    if (i < N_NNZ) atomicAdd(&row_ptr[row[i] + 1], 1);
}

__global__ __launch_bounds__(SCAN_BS)
void scan_a_kernel(int* __restrict__ data, int* __restrict__ blocksum, int n) {
    __shared__ int sh[SCAN_BS];
    int gid = blockIdx.x * SCAN_BS + threadIdx.x;
    int v = (gid < n) ? data[gid] : 0;
    sh[threadIdx.x] = v;
    __syncthreads();
#pragma unroll
    for (int o = 1; o < SCAN_BS; o <<= 1) {
        int t = (threadIdx.x >= o) ? sh[threadIdx.x - o] : 0;
        __syncthreads();
        sh[threadIdx.x] += t;
        __syncthreads();
    }
    if (gid < n) data[gid] = sh[threadIdx.x];
    if (threadIdx.x == SCAN_BS - 1) blocksum[blockIdx.x] = sh[threadIdx.x];
}

__global__ __launch_bounds__(SCAN_BS)
void scan_b_kernel(int* __restrict__ blocksum, int nb) {
    __shared__ int sh[SCAN_BS];
    int v = (threadIdx.x < nb) ? blocksum[threadIdx.x] : 0;
    sh[threadIdx.x] = v;
    __syncthreads();
#pragma unroll
    for (int o = 1; o < SCAN_BS; o <<= 1) {
        int t = (threadIdx.x >= o) ? sh[threadIdx.x - o] : 0;
        __syncthreads();
        sh[threadIdx.x] += t;
        __syncthreads();
    }
    if (threadIdx.x < nb) blocksum[threadIdx.x] = sh[threadIdx.x];
}

__global__ __launch_bounds__(SCAN_BS)
void scan_c_kernel(int* __restrict__ data, const int* __restrict__ blocksum,
                   int* __restrict__ work, int n) {
    int gid = blockIdx.x * SCAN_BS + threadIdx.x;
    if (gid >= n) return;
    int v = data[gid];
    if (blockIdx.x > 0) v += blocksum[blockIdx.x - 1];
    data[gid] = v;
    work[gid] = v;
}

__global__ void scatter_kernel(const int* __restrict__ row, const int* __restrict__ col,
                               const float* __restrict__ val,
                               int* __restrict__ work,
                               int* __restrict__ csr_col, float* __restrict__ csr_val) {
    int i = blockIdx.x * blockDim.x + threadIdx.x;
    if (i >= N_NNZ) return;
    int pos = atomicAdd(&work[row[i]], 1);
    csr_col[pos] = col[i];
    csr_val[pos] = val[i];
}

// ================= fused CSR aggregation ======================================
template <int F, int VPL>
__global__ __launch_bounds__(256)
void csr_agg_kernel(const int* __restrict__ row_ptr,
                    const int* __restrict__ csr_col,
                    const float* __restrict__ csr_val,
                    const float* __restrict__ X,
                    const float* __restrict__ bias,
                    float* __restrict__ Xout,
                    float* __restrict__ colsum) {
    __shared__ float scol[F];
    const int tid  = threadIdx.x;
    const int wid  = tid >> 5;
    const int lane = tid & 31;

    if (tid < F) scol[tid] = 0.0f;
    __syncthreads();

    float bz[VPL];
#pragma unroll
    for (int j = 0; j < VPL; j++) bz[j] = bias[lane * VPL + j];

    float csum[VPL];
#pragma unroll
    for (int j = 0; j < VPL; j++) csum[j] = 0.0f;

    const int rowBase = blockIdx.x * 32 + wid * 4;

#pragma unroll
    for (int rr = 0; rr < 4; rr++) {
        const int r = rowBase + rr;
        const int start = row_ptr[r];
        const int end   = row_ptr[r + 1];

        float acc[VPL];
#pragma unroll
        for (int j = 0; j < VPL; j++) acc[j] = 0.0f;

        for (int base = start; base < end; base += 32) {
            int idx = base + lane;
            int   cv = 0;
            float vv = 0.0f;
            if (idx < end) { cv = csr_col[idx]; vv = csr_val[idx]; }
            int count = min(32, end - base);
            for (int j = 0; j < count; j++) {
                int   c = __shfl_sync(0xffffffffu, cv, j);
                float v = __shfl_sync(0xffffffffu, vv, j);
                const float* xr = X + (size_t)c * F;
                if (VPL == 4) {
                    float4 x4 = reinterpret_cast<const float4*>(xr)[lane];
                    acc[0] = fmaf(v, x4.x, acc[0]);
                    acc[1] = fmaf(v, x4.y, acc[1]);
                    acc[2] = fmaf(v, x4.z, acc[2]);
                    acc[3] = fmaf(v, x4.w, acc[3]);
                } else {
                    float2 x2 = reinterpret_cast<const float2*>(xr)[lane];
                    acc[0] = fmaf(v, x2.x, acc[0]);
                    acc[1] = fmaf(v, x2.y, acc[1]);
                }
            }
        }

#pragma unroll
        for (int j = 0; j < VPL; j++) {
            float o = fmaxf(acc[j] + bz[j], 0.0f);
            acc[j] = o;
            csum[j] += o;
        }
        float* od = Xout + (size_t)r * F;
        if (VPL == 4) {
            float4 o4 = make_float4(acc[0], acc[1], acc[2], acc[3]);
            reinterpret_cast<float4*>(od)[lane] = o4;
        } else {
            float2 o2 = make_float2(acc[0], acc[1]);
            reinterpret_cast<float2*>(od)[lane] = o2;
        }
    }

#pragma unroll
    for (int j = 0; j < VPL; j++)
        atomicAdd(&scol[lane * VPL + j], csum[j]);
    __syncthreads();
    if (tid < F) atomicAdd(&colsum[tid], scol[tid]);
}

__global__ void zero_colsum_kernel(float* __restrict__ colsum, int F) {
    if (threadIdx.x < F) colsum[threadIdx.x] = 0.0f;
}

// ================= GEMM common helpers =======================================
__device__ __forceinline__ uint32_t pack_bf16x2(float f_up, float f_lo) {
    uint32_t r;
    asm("cvt.rn.bf16x2.f32 %0, %1, %2;" : "=r"(r) : "f"(f_up), "f"(f_lo));
    return r;
}

__device__ __forceinline__ uint32_t pack_f16x2(float f_up, float f_lo) {
    uint32_t r;
    asm("cvt.rn.f16x2.f32 %0, %1, %2;" : "=r"(r) : "f"(f_up), "f"(f_lo));
    return r;
}

#define MMA_BF16(d, A0, A1, A2, A3, B0, B1)                                     \
    asm volatile(                                                               \
        "mma.sync.aligned.m16n8k16.row.col.f32.bf16.bf16.f32 "                  \
        "{%0,%1,%2,%3}, {%4,%5,%6,%7}, {%8,%9}, {%0,%1,%2,%3};"                 \
        : "+f"((d)[0]), "+f"((d)[1]), "+f"((d)[2]), "+f"((d)[3])                \
        : "r"(A0), "r"(A1), "r"(A2), "r"(A3), "r"(B0), "r"(B1));

#define MMA_F16(d, A0, A1, A2, A3, B0, B1)                                      \
    asm volatile(                                                               \
        "mma.sync.aligned.m16n8k16.row.col.f32.f16.f16.f32 "                    \
        "{%0,%1,%2,%3}, {%4,%5,%6,%7}, {%8,%9}, {%0,%1,%2,%3};"                 \
        : "+f"((d)[0]), "+f"((d)[1]), "+f"((d)[2]), "+f"((d)[3])                \
        : "r"(A0), "r"(A1), "r"(A2), "r"(A3), "r"(B0), "r"(B1));

// ================= fp16-A GEMM (L0): A single fp16, B fp16 hi+lo, 2 terms ====
// C[N,M] = A[N,K] @ B[K,M], block tile 128x128, BK=16, 8 warps.
__global__ __launch_bounds__(256)
void f16a_gemm_kernel(const float* __restrict__ A, const float* __restrict__ B,
                      float* __restrict__ C, int N, int K, int M) {
    constexpr int BN_T = 128;
    constexpr int NI = 8;
    constexpr int SA = 136;
    constexpr int SB = 136;

    __shared__ uint32_t As_h[8][SA];
    __shared__ uint32_t Bs_h[8][SB], Bs_l[8][SB];

    const int tid  = threadIdx.x;
    const int wid  = tid >> 5;
    const int lane = tid & 31;
    const int g    = lane >> 2;
    const int tg   = lane & 3;
    const int wr   = (wid & 3) * 32;
    const int wc   = (wid >> 2) * 64;
    const int rowBase = blockIdx.y * 128;
    const int colBase = 0;

    float acc[2][NI][4];
#pragma unroll
    for (int mi = 0; mi < 2; mi++)
#pragma unroll
        for (int ni = 0; ni < NI; ni++)
#pragma unroll
            for (int r = 0; r < 4; r++) acc[mi][ni][r] = 0.0f;

    const int ar = tid >> 1;
    const int ak = (tid & 1) * 8;
    const int k2a = (tid & 1) * 4;
    const bool arOK = (rowBase + ar) < N;
    const float* Arow = A + (size_t)(rowBase + ar) * K;

    const int k2b = tid / 32;          // 0..7 (k-pair)
    const int c4  = tid % 32;          // float4 col group

    float  fa[8];
    float4 v0, v1;

    auto load_global = [&](int k0) {
#pragma unroll
        for (int j = 0; j < 8; j++) {
            int gk = k0 + ak + j;
            fa[j] = (arOK && gk < K) ? Arow[gk] : 0.0f;
        }
        int gk0 = k0 + 2 * k2b;
        v0 = (gk0 < K) ? *reinterpret_cast<const float4*>(
                             B + (size_t)gk0 * M + colBase + c4 * 4)
                       : make_float4(0.f, 0.f, 0.f, 0.f);
        v1 = (gk0 + 1 < K) ? *reinterpret_cast<const float4*>(
                                 B + (size_t)(gk0 + 1) * M + colBase + c4 * 4)
                           : make_float4(0.f, 0.f, 0.f, 0.f);
    };

    auto store_smem = [&]() {
        // A: single fp16 format — 1 cvt + 1 STS per 2 elements
#pragma unroll
        for (int j = 0; j < 4; j++)
            As_h[k2a + j][ar] = pack_f16x2(fa[2 * j + 1], fa[2 * j]);
        // B: fp16 hi + lo split (tiny tile, cost negligible)
        const float e0[4] = {v0.x, v0.y, v0.z, v0.w};
        const float e1[4] = {v1.x, v1.y, v1.z, v1.w};
#pragma unroll
        for (int e = 0; e < 4; e++) {
            int col = c4 * 4 + e;
            float b0 = e0[e], b1 = e1[e];
            uint32_t h = pack_f16x2(b1, b0);
            __half2 h2 = *reinterpret_cast<__half2*>(&h);
            float hf0 = __half2float(__low2half(h2));
            float hf1 = __half2float(__high2half(h2));
            Bs_h[k2b][col] = h;
            Bs_l[k2b][col] = pack_f16x2(b1 - hf1, b0 - hf0);
        }
    };

    const int KT = (K + 15) / 16;
    load_global(0);

    for (int kt = 0; kt < KT; kt++) {
        store_smem();
        __syncthreads();
        if (kt + 1 < KT) load_global((kt + 1) * 16);

        uint32_t ah[2][4];
#pragma unroll
        for (int mi = 0; mi < 2; mi++) {
            int r0 = wr + mi * 16 + g;
            ah[mi][0] = As_h[tg][r0];
            ah[mi][1] = As_h[tg][r0 + 8];
            ah[mi][2] = As_h[tg + 4][r0];
            ah[mi][3] = As_h[tg + 4][r0 + 8];
        }
#pragma unroll
        for (int ni = 0; ni < NI; ni++) {
            int col = wc + ni * 8 + g;
            uint32_t bh0 = Bs_h[tg][col];
            uint32_t bh1 = Bs_h[tg + 4][col];
            uint32_t bl0 = Bs_l[tg][col];
            uint32_t bl1 = Bs_l[tg + 4][col];
#pragma unroll
            for (int mi = 0; mi < 2; mi++) {
                MMA_F16(acc[mi][ni], ah[mi][0], ah[mi][1], ah[mi][2], ah[mi][3],
                        bh0, bh1);
                MMA_F16(acc[mi][ni], ah[mi][0], ah[mi][1], ah[mi][2], ah[mi][3],
                        bl0, bl1);
            }
        }
        __syncthreads();
    }

#pragma unroll
    for (int mi = 0; mi < 2; mi++) {
#pragma unroll
        for (int ni = 0; ni < NI; ni++) {
            int col = colBase + wc + ni * 8 + tg * 2;
            int r0  = rowBase + wr + mi * 16 + g;
            if (r0 < N) {
                float2 v = make_float2(acc[mi][ni][0], acc[mi][ni][1]);
                *reinterpret_cast<float2*>(C + (size_t)r0 * M + col) = v;
            }
            if (r0 + 8 < N) {
                float2 v = make_float2(acc[mi][ni][2], acc[mi][ni][3]);
                *reinterpret_cast<float2*>(C + (size_t)(r0 + 8) * M + col) = v;
            }
        }
    }
}

// ================= bf16x3 GEMM (layers 1,2) ==================================
template <int BN_T>
__global__ __launch_bounds__(256)
void bf16x3_gemm_kernel(const float* __restrict__ A, const float* __restrict__ B,
                        float* __restrict__ C, int N, int K, int M) {
    constexpr int NI = BN_T / 16;
    constexpr int SA = 136;
    constexpr int SB = BN_T + 8;
    constexpr int BIDS = 8 * (BN_T / 4);

    __shared__ uint32_t As_hi[8][SA], As_lo[8][SA];
    __shared__ uint32_t Bs_hi[8][SB], Bs_lo[8][SB];

    const int tid  = threadIdx.x;
    const int wid  = tid >> 5;
    const int lane = tid & 31;
    const int g    = lane >> 2;
    const int tg   = lane & 3;
    const int wr   = (wid & 3) * 32;
    const int wc   = (wid >> 2) * (BN_T / 2);
    const int rowBase = blockIdx.y * 128;
    const int colBase = blockIdx.x * BN_T;

    float acc[2][NI][4];
#pragma unroll
    for (int mi = 0; mi < 2; mi++)
#pragma unroll
        for (int ni = 0; ni < NI; ni++)
#pragma unroll
            for (int r = 0; r < 4; r++) acc[mi][ni][r] = 0.0f;

    const int ar = tid >> 1;
    const int ak = (tid & 1) * 8;
    const int k2a = (tid & 1) * 4;
    const bool arOK = (rowBase + ar) < N;
    const float* Arow = A + (size_t)(rowBase + ar) * K;

    const bool bActive = tid < BIDS;
    const int k2b = tid / (BN_T / 4);
    const int c4  = tid % (BN_T / 4);

    float  fa[8];
    float4 v0, v1;

    auto load_global = [&](int k0) {
#pragma unroll
        for (int j = 0; j < 8; j++) {
            int gk = k0 + ak + j;
            fa[j] = (arOK && gk < K) ? Arow[gk] : 0.0f;
        }
        if (bActive) {
            int gk0 = k0 + 2 * k2b;
            v0 = (gk0 < K) ? *reinterpret_cast<const float4*>(
                                 B + (size_t)gk0 * M + colBase + c4 * 4)
                           : make_float4(0.f, 0.f, 0.f, 0.f);
            v1 = (gk0 + 1 < K) ? *reinterpret_cast<const float4*>(
                                     B + (size_t)(gk0 + 1) * M + colBase + c4 * 4)
                               : make_float4(0.f, 0.f, 0.f, 0.f);
        }
    };

    auto store_smem = [&]() {
#pragma unroll
        for (int j = 0; j < 4; j++) {
            float f0 = fa[2 * j], f1 = fa[2 * j + 1];
            uint32_t h = pack_bf16x2(f1, f0);
            float h0 = __uint_as_float(h << 16);
            float h1 = __uint_as_float(h & 0xFFFF0000u);
            uint32_t l = pack_bf16x2(f1 - h1, f0 - h0);
            As_hi[k2a + j][ar] = h;
            As_lo[k2a + j][ar] = l;
        }
        if (bActive) {
            const float e0[4] = {v0.x, v0.y, v0.z, v0.w};
            const float e1[4] = {v1.x, v1.y, v1.z, v1.w};
#pragma unroll
            for (int e = 0; e < 4; e++) {
                int col = c4 * 4 + e;
                uint32_t h = pack_bf16x2(e1[e], e0[e]);
                float h0 = __uint_as_float(h << 16);
                float h1 = __uint_as_float(h & 0xFFFF0000u);
                uint32_t l = pack_bf16x2(e1[e] - h1, e0[e] - h0);
                Bs_hi[k2b][col] = h;
                Bs_lo[k2b][col] = l;
            }
        }
    };

    const int KT = (K + 15) / 16;
    load_global(0);

    for (int kt = 0; kt < KT; kt++) {
        store_smem();
        __syncthreads();
        if (kt + 1 < KT) load_global((kt + 1) * 16);

        uint32_t ah[2][4], al[2][4];
#pragma unroll
        for (int mi = 0; mi < 2; mi++) {
            int r0 = wr + mi * 16 + g;
            ah[mi][0] = As_hi[tg][r0];
            ah[mi][1] = As_hi[tg][r0 + 8];
            ah[mi][2] = As_hi[tg + 4][r0];
            ah[mi][3] = As_hi[tg + 4][r0 + 8];
            al[mi][0] = As_lo[tg][r0];
            al[mi][1] = As_lo[tg][r0 + 8];
            al[mi][2] = As_lo[tg + 4][r0];
            al[mi][3] = As_lo[tg + 4][r0 + 8];
        }
#pragma unroll
        for (int ni = 0; ni < NI; ni++) {
            int col = wc + ni * 8 + g;
            uint32_t bh0 = Bs_hi[tg][col];
            uint32_t bh1 = Bs_hi[tg + 4][col];
            uint32_t bl0 = Bs_lo[tg][col];
            uint32_t bl1 = Bs_lo[tg + 4][col];
#pragma unroll
            for (int mi = 0; mi < 2; mi++) {
                MMA_BF16(acc[mi][ni], ah[mi][0], ah[mi][1], ah[mi][2], ah[mi][3],
                         bh0, bh1);
                MMA_BF16(acc[mi][ni], al[mi][0], al[mi][1], al[mi][2], al[mi][3],
                         bh0, bh1);
                MMA_BF16(acc[mi][ni], ah[mi][0], ah[mi][1], ah[mi][2], ah[mi][3],
                         bl0, bl1);
            }
        }
        __syncthreads();
    }

#pragma unroll
    for (int mi = 0; mi < 2; mi++) {
#pragma unroll
        for (int ni = 0; ni < NI; ni++) {
            int col = colBase + wc + ni * 8 + tg * 2;
            int r0  = rowBase + wr + mi * 16 + g;
            if (r0 < N) {
                float2 v = make_float2(acc[mi][ni][0], acc[mi][ni][1]);
                *reinterpret_cast<float2*>(C + (size_t)r0 * M + col) = v;
            }
            if (r0 + 8 < N) {
                float2 v = make_float2(acc[mi][ni][2], acc[mi][ni][3]);
                *reinterpret_cast<float2*>(C + (size_t)(r0 + 8) * M + col) = v;
            }
        }
    }
}

// ---------------- PairNorm (PN-SI) -------------------------------------------
template <int PER>
__global__ __launch_bounds__(256)
void pairnorm_kernel(float* __restrict__ X, const float* __restrict__ colsum,
                     int N, int F) {
    int warp = (blockIdx.x * blockDim.x + threadIdx.x) >> 5;
    int lane = threadIdx.x & 31;
    if (warp >= N) return;
    float* xr = X + (long)warp * F;
    const float inv_n = 1.0f / (float)N_NODES;
    float vals[PER];
    float sumsq = 0.0f;
#pragma unroll
    for (int j = 0; j < PER; j++) {
        int f = lane + j * 32;
        float m = colsum[f] * inv_n;
        float v = xr[f] - m;
        vals[j] = v;
        sumsq = fmaf(v, v, sumsq);
    }
#pragma unroll
    for (int o = 16; o > 0; o >>= 1)
        sumsq += __shfl_xor_sync(0xffffffffu, sumsq, o);
    float inv = rsqrtf(1e-6f + sumsq);
#pragma unroll
    for (int j = 0; j < PER; j++)
        xr[lane + j * 32] = vals[j] * inv;
}

// ---------------- decode ------------------------------------------------------
__global__ __launch_bounds__(128)
void decode_kernel(const float* __restrict__ X, const int* __restrict__ pos,
                   const int* __restrict__ neg, float* __restrict__ out) {
    int warp = (blockIdx.x * blockDim.x + threadIdx.x) >> 5;
    int lane = threadIdx.x & 31;
    if (warp >= N_EDGES) return;
    const int* e = (warp < N_POS) ? (pos + 2 * warp) : (neg + 2 * (warp - N_POS));
    int a = e[0];
    int bnode = e[1];
    const float* xa = X + (long)a * F_OUT;
    const float* xb = X + (long)bnode * F_OUT;
    float s = xa[lane] * xb[lane] + xa[lane + 32] * xb[lane + 32];
#pragma unroll
    for (int o = 16; o > 0; o >>= 1)
        s += __shfl_xor_sync(0xffffffffu, s, o);
    if (lane == 0) out[warp] = 1.0f / (1.0f + expf(-s));
}

// ---------------- host orchestration -----------------------------------------
static void run_layer(const float* x_in, int K, const float* W, const float* b,
                      int M, float* support, float* x_out, float* colsum,
                      const int* row_ptr, const int* csr_col, const float* csr_val,
                      bool use_f16a) {
    dim3 gGemm(1, (N_NODES + 127) / 128);
    if (use_f16a)
        f16a_gemm_kernel<<<gGemm, 256>>>(x_in, W, support, N_NODES, K, M);
    else if (M == 128)
        bf16x3_gemm_kernel<128><<<gGemm, 256>>>(x_in, W, support, N_NODES, K, M);
    else
        bf16x3_gemm_kernel<64><<<gGemm, 256>>>(x_in, W, support, N_NODES, K, M);

    zero_colsum_kernel<<<1, 128>>>(colsum, M);

    int aggBlocks = N_NODES / 32;   // 3125
    if (M == 128)
        csr_agg_kernel<128, 4><<<aggBlocks, 256>>>(row_ptr, csr_col, csr_val,
                                                   support, b, x_out, colsum);
    else
        csr_agg_kernel<64, 2><<<aggBlocks, 256>>>(row_ptr, csr_col, csr_val,
                                                  support, b, x_out, colsum);

    int pnBlocks = (N_NODES * 32 + 255) / 256;
    if (M == 128)
        pairnorm_kernel<4><<<pnBlocks, 256>>>(x_out, colsum, N_NODES, M);
    else
        pairnorm_kernel<2><<<pnBlocks, 256>>>(x_out, colsum, N_NODES, M);
}

extern "C" void kernel_launch(void* const* d_in, const int* in_sizes, int n_in,
                              void* d_out, int out_size) {
    const float* in_feature = (const float*)d_in[0];
    const int*   adj_row    = (const int*)d_in[1];
    const int*   adj_col    = (const int*)d_in[2];
    const float* adj_val    = (const float*)d_in[3];
    const int*   pos_edge   = (const int*)d_in[4];
    const int*   neg_edge   = (const int*)d_in[5];
    const float* W0 = (const float*)d_in[6];
    const float* b0 = (const float*)d_in[7];
    const float* W1 = (const float*)d_in[8];
    const float* b1 = (const float*)d_in[9];
    const float* W2 = (const float*)d_in[10];
    const float* b2 = (const float*)d_in[11];
    float* out = (float*)d_out;

    float *support, *x, *colsum, *csr_val;
    int *row_ptr, *row_work, *csr_col, *blocksum;
    cudaGetSymbolAddress((void**)&support,  g_support);
    cudaGetSymbolAddress((void**)&x,        g_x);
    cudaGetSymbolAddress((void**)&colsum,   g_colsum);
    cudaGetSymbolAddress((void**)&row_ptr,  g_row_ptr);
    cudaGetSymbolAddress((void**)&row_work, g_row_work);
    cudaGetSymbolAddress((void**)&csr_col,  g_csr_col);
    cudaGetSymbolAddress((void**)&csr_val,  g_csr_val);
    cudaGetSymbolAddress((void**)&blocksum, g_blocksum);

    // ---- build CSR (once; reused by all 3 layers) ----
    hist_zero_kernel<<<(N_NODES + 1 + 255) / 256, 256>>>(row_ptr);
    hist_kernel<<<(N_NNZ + 255) / 256, 256>>>(adj_row, row_ptr);
    scan_a_kernel<<<SCAN_NB, SCAN_BS>>>(row_ptr, blocksum, N_NODES + 1);
    scan_b_kernel<<<1, SCAN_BS>>>(blocksum, SCAN_NB);
    scan_c_kernel<<<SCAN_NB, SCAN_BS>>>(row_ptr, blocksum, row_work, N_NODES + 1);
    scatter_kernel<<<(N_NNZ + 255) / 256, 256>>>(adj_row, adj_col, adj_val,
                                                 row_work, csr_col, csr_val);

    // ---- 3 GCN layers ----
    run_layer(in_feature, F_IN, W0, b0, F_HID, support, x, colsum,
              row_ptr, csr_col, csr_val, /*use_f16a=*/true);
    run_layer(x, F_HID, W1, b1, F_HID, support, x, colsum,
              row_ptr, csr_col, csr_val, /*use_f16a=*/false);
    run_layer(x, F_HID, W2, b2, F_OUT, support, x, colsum,
              row_ptr, csr_col, csr_val, /*use_f16a=*/false);

    // ---- decode ----
    decode_kernel<<<(N_EDGES * 32 + 127) / 128, 128>>>(x, pos_edge, neg_edge, out);
}

// round 12
// speedup vs baseline: 3.6637x; 1.3784x over previous
#include <cuda_runtime.h>
#include <cuda_fp16.h>
#include <math.h>
#include <stdint.h>

#define N_NODES 100000
#define N_NNZ   1000000
#define F_IN    1433
#define F_HID   128
#define F_OUT   64
#define N_POS   20000
#define N_EDGES 40000

#define SCAN_BS 1024
#define SCAN_NB ((N_NODES + 1 + SCAN_BS - 1) / SCAN_BS)   // 98

// ---------------- scratch (static device globals; no allocation) -------------
__device__ float g_support[(size_t)N_NODES * F_HID];
__device__ float g_x[(size_t)N_NODES * F_HID];
__device__ float g_colsum[F_HID];
__device__ int   g_row_ptr[N_NODES + 1];
__device__ int   g_row_work[N_NODES + 1];
__device__ int   g_csr_col[N_NNZ];
__device__ float g_csr_val[N_NNZ];
__device__ int   g_blocksum[SCAN_NB];

// ================= helpers ===================================================
__device__ __forceinline__ uint32_t smem_u32(const void* p) {
    uint32_t a;
    asm("{ .reg .u64 t; cvta.to.shared.u64 t, %1; cvt.u32.u64 %0, t; }"
        : "=r"(a) : "l"(p));
    return a;
}

__device__ __forceinline__ uint32_t pack_f16x2(float f_up, float f_lo) {
    uint32_t r;
    asm("cvt.rn.f16x2.f32 %0, %1, %2;" : "=r"(r) : "f"(f_up), "f"(f_lo));
    return r;
}

#define MMA_F16(d, A0, A1, A2, A3, B0, B1)                                      \
    asm volatile(                                                               \
        "mma.sync.aligned.m16n8k16.row.col.f32.f16.f16.f32 "                    \
        "{%0,%1,%2,%3}, {%4,%5,%6,%7}, {%8,%9}, {%0,%1,%2,%3};"                 \
        : "+f"((d)[0]), "+f"((d)[1]), "+f"((d)[2]), "+f"((d)[3])                \
        : "r"(A0), "r"(A1), "r"(A2), "r"(A3), "r"(B0), "r"(B1));

#define LDMATRIX_X4(r0, r1, r2, r3, addr)                                       \
    asm volatile(                                                               \
        "ldmatrix.sync.aligned.m8n8.x4.shared.b16 {%0,%1,%2,%3}, [%4];"         \
        : "=r"(r0), "=r"(r1), "=r"(r2), "=r"(r3) : "r"(addr));

// ================= fp16 1-term tensor-core GEMM ==============================
// C[Nrows, NC] = A[Nrows, K] (fp32) @ W[K, NC] (fp32), computed in fp16.
// Block: 128 rows x NC cols, BK = 32. 8 warps: 4 row-groups x (NC/64) col-groups.
// A smem: row-major fp16, 128 rows x 32 halves, 80B stride (ldmatrix-friendly).
// B smem: Bs[k2][col] packed fp16x2 (k-pair), SB stride conflict-free.
#define A_STRIDE 80

template <int NC>
__global__ __launch_bounds__(256)
void f16_gemm_kernel(const float* __restrict__ A, const float* __restrict__ B,
                     float* __restrict__ C, int Nrows, int K) {
    constexpr int NI = NC / 16;          // 8-col subtiles per warp
    constexpr int SB = NC + 8;           // uint32 stride
    constexpr int BITERS = (16 * (NC / 4)) / 256;  // B-load iters (2 or 1)

    __shared__ __align__(16) uint8_t As[128 * A_STRIDE];
    __shared__ uint32_t Bs[16][SB];

    const int tid  = threadIdx.x;
    const int wid  = tid >> 5;
    const int lane = tid & 31;
    const int g    = lane >> 2;
    const int tg   = lane & 3;
    const int wr   = (wid & 3) * 32;
    const int wc   = (wid >> 2) * (NC / 2);
    const int rowBase = blockIdx.x * 128;

    const uint32_t asBase = smem_u32(As);

    float acc[2][NI][4];
#pragma unroll
    for (int mi = 0; mi < 2; mi++)
#pragma unroll
        for (int ni = 0; ni < NI; ni++)
#pragma unroll
            for (int r = 0; r < 4; r++) acc[mi][ni][r] = 0.0f;

    // A loader: warp w -> rows w*16 .. w*16+15, lane -> k offset (coalesced)
    const int aRow0 = wid * 16;
    float fa[16];

    auto load_A = [&](int kt) {
        const int kglob = kt * 32 + lane;
        const bool kOK = kglob < K;
#pragma unroll
        for (int i = 0; i < 16; i++) {
            const int gr = rowBase + aRow0 + i;
            fa[i] = (kOK && gr < Nrows) ? A[(size_t)gr * K + kglob] : 0.0f;
        }
    };

    auto store_A = [&]() {
#pragma unroll
        for (int i = 0; i < 16; i++) {
            const uint32_t addr = asBase + (aRow0 + i) * A_STRIDE + lane * 2;
            const __half h = __float2half_rn(fa[i]);
            const unsigned short hu = *reinterpret_cast<const unsigned short*>(&h);
            asm volatile("st.shared.b16 [%0], %1;" :: "r"(addr), "h"(hu) : "memory");
        }
    };

    // ldmatrix source address (per lane), parameterized by (mi, ks) at use site
    const int lmRow = lane & 15;
    const int lmKoff = (lane >> 4) * 16;   // bytes

    const int KT = (K + 31) / 32;
    load_A(0);

    for (int kt = 0; kt < KT; kt++) {
        store_A();

        // ---- B tile: 32 k x NC cols, coalesced float4 along n, pack k-pairs --
#pragma unroll
        for (int it = 0; it < BITERS; it++) {
            const int slot = tid + it * 256;
            const int kp = slot / (NC / 4);        // k-pair 0..15
            const int n4 = slot % (NC / 4);
            const int kg0 = kt * 32 + 2 * kp;
            float4 v0 = make_float4(0.f, 0.f, 0.f, 0.f);
            float4 v1 = make_float4(0.f, 0.f, 0.f, 0.f);
            if (kg0 < K)
                v0 = *reinterpret_cast<const float4*>(B + (size_t)kg0 * NC + n4 * 4);
            if (kg0 + 1 < K)
                v1 = *reinterpret_cast<const float4*>(B + (size_t)(kg0 + 1) * NC + n4 * 4);
            Bs[kp][n4 * 4 + 0] = pack_f16x2(v1.x, v0.x);
            Bs[kp][n4 * 4 + 1] = pack_f16x2(v1.y, v0.y);
            Bs[kp][n4 * 4 + 2] = pack_f16x2(v1.z, v0.z);
            Bs[kp][n4 * 4 + 3] = pack_f16x2(v1.w, v0.w);
        }
        __syncthreads();

        if (kt + 1 < KT) load_A(kt + 1);

#pragma unroll
        for (int ks = 0; ks < 2; ks++) {
            uint32_t a[2][4];
#pragma unroll
            for (int mi = 0; mi < 2; mi++) {
                const uint32_t addr = asBase +
                    (wr + mi * 16 + lmRow) * A_STRIDE + ks * 32 + lmKoff;
                LDMATRIX_X4(a[mi][0], a[mi][1], a[mi][2], a[mi][3], addr);
            }
#pragma unroll
            for (int ni = 0; ni < NI; ni++) {
                const int col = wc + ni * 8 + g;
                const uint32_t b0 = Bs[ks * 8 + tg][col];
                const uint32_t b1 = Bs[ks * 8 + tg + 4][col];
#pragma unroll
                for (int mi = 0; mi < 2; mi++) {
                    MMA_F16(acc[mi][ni], a[mi][0], a[mi][1], a[mi][2], a[mi][3],
                            b0, b1);
                }
            }
        }
        __syncthreads();
    }

    // ---- store C ----
#pragma unroll
    for (int mi = 0; mi < 2; mi++) {
#pragma unroll
        for (int ni = 0; ni < NI; ni++) {
            const int col = wc + ni * 8 + tg * 2;
            const int r0  = rowBase + wr + mi * 16 + g;
            if (r0 < Nrows) {
                float2 v = make_float2(acc[mi][ni][0], acc[mi][ni][1]);
                *reinterpret_cast<float2*>(C + (size_t)r0 * NC + col) = v;
            }
            if (r0 + 8 < Nrows) {
                float2 v = make_float2(acc[mi][ni][2], acc[mi][ni][3]);
                *reinterpret_cast<float2*>(C + (size_t)(r0 + 8) * NC + col) = v;
            }
        }
    }
}

// ================= CSR build ==================================================
__global__ void hist_zero_kernel(int* __restrict__ row_ptr) {
    int i = blockIdx.x * blockDim.x + threadIdx.x;
    if (i <= N_NODES) row_ptr[i] = 0;
}

__global__ void hist_kernel(const int* __restrict__ row, int* __restrict__ row_ptr) {
    int i = blockIdx.x * blockDim.x + threadIdx.x;
    if (i < N_NNZ) atomicAdd(&row_ptr[row[i] + 1], 1);
}

__global__ __launch_bounds__(SCAN_BS)
void scan_a_kernel(int* __restrict__ data, int* __restrict__ blocksum, int n) {
    __shared__ int sh[SCAN_BS];
    int gid = blockIdx.x * SCAN_BS + threadIdx.x;
    int v = (gid < n) ? data[gid] : 0;
    sh[threadIdx.x] = v;
    __syncthreads();
#pragma unroll
    for (int o = 1; o < SCAN_BS; o <<= 1) {
        int t = (threadIdx.x >= o) ? sh[threadIdx.x - o] : 0;
        __syncthreads();
        sh[threadIdx.x] += t;
        __syncthreads();
    }
    if (gid < n) data[gid] = sh[threadIdx.x];
    if (threadIdx.x == SCAN_BS - 1) blocksum[blockIdx.x] = sh[threadIdx.x];
}

__global__ __launch_bounds__(SCAN_BS)
void scan_b_kernel(int* __restrict__ blocksum, int nb) {
    __shared__ int sh[SCAN_BS];
    int v = (threadIdx.x < nb) ? blocksum[threadIdx.x] : 0;
    sh[threadIdx.x] = v;
    __syncthreads();
#pragma unroll
    for (int o = 1; o < SCAN_BS; o <<= 1) {
        int t = (threadIdx.x >= o) ? sh[threadIdx.x - o] : 0;
        __syncthreads();
        sh[threadIdx.x] += t;
        __syncthreads();
    }
    if (threadIdx.x < nb) blocksum[threadIdx.x] = sh[threadIdx.x];
}

__global__ __launch_bounds__(SCAN_BS)
void scan_c_kernel(int* __restrict__ data, const int* __restrict__ blocksum,
                   int* __restrict__ work, int n) {
    int gid = blockIdx.x * SCAN_BS + threadIdx.x;
    if (gid >= n) return;
    int v = data[gid];
    if (blockIdx.x > 0) v += blocksum[blockIdx.x - 1];
    data[gid] = v;
    work[gid] = v;
}

__global__ void scatter_kernel(const int* __restrict__ row, const int* __restrict__ col,
                               const float* __restrict__ val,
                               int* __restrict__ work,
                               int* __restrict__ csr_col, float* __restrict__ csr_val) {
    int i = blockIdx.x * blockDim.x + threadIdx.x;
    if (i >= N_NNZ) return;
    int pos = atomicAdd(&work[row[i]], 1);
    csr_col[pos] = col[i];
    csr_val[pos] = val[i];
}

// ================= fused CSR aggregation ======================================
template <int F, int VPL>
__global__ __launch_bounds__(256)
void csr_agg_kernel(const int* __restrict__ row_ptr,
                    const int* __restrict__ csr_col,
                    const float* __restrict__ csr_val,
                    const float* __restrict__ X,
                    const float* __restrict__ bias,
                    float* __restrict__ Xout,
                    float* __restrict__ colsum) {
    __shared__ float scol[F];
    const int tid  = threadIdx.x;
    const int wid  = tid >> 5;
    const int lane = tid & 31;

    if (tid < F) scol[tid] = 0.0f;
    __syncthreads();

    float bz[VPL];
#pragma unroll
    for (int j = 0; j < VPL; j++) bz[j] = bias[lane * VPL + j];

    float csum[VPL];
#pragma unroll
    for (int j = 0; j < VPL; j++) csum[j] = 0.0f;

    const int rowBase = blockIdx.x * 32 + wid * 4;

#pragma unroll
    for (int rr = 0; rr < 4; rr++) {
        const int r = rowBase + rr;
        const int start = row_ptr[r];
        const int end   = row_ptr[r + 1];

        float acc[VPL];
#pragma unroll
        for (int j = 0; j < VPL; j++) acc[j] = 0.0f;

        for (int base = start; base < end; base += 32) {
            int idx = base + lane;
            int   cv = 0;
            float vv = 0.0f;
            if (idx < end) { cv = csr_col[idx]; vv = csr_val[idx]; }
            int count = min(32, end - base);
            for (int j = 0; j < count; j++) {
                int   c = __shfl_sync(0xffffffffu, cv, j);
                float v = __shfl_sync(0xffffffffu, vv, j);
                const float* xr = X + (size_t)c * F;
                if (VPL == 4) {
                    float4 x4 = reinterpret_cast<const float4*>(xr)[lane];
                    acc[0] = fmaf(v, x4.x, acc[0]);
                    acc[1] = fmaf(v, x4.y, acc[1]);
                    acc[2] = fmaf(v, x4.z, acc[2]);
                    acc[3] = fmaf(v, x4.w, acc[3]);
                } else {
                    float2 x2 = reinterpret_cast<const float2*>(xr)[lane];
                    acc[0] = fmaf(v, x2.x, acc[0]);
                    acc[1] = fmaf(v, x2.y, acc[1]);
                }
            }
        }

#pragma unroll
        for (int j = 0; j < VPL; j++) {
            float o = fmaxf(acc[j] + bz[j], 0.0f);
            acc[j] = o;
            csum[j] += o;
        }
        float* od = Xout + (size_t)r * F;
        if (VPL == 4) {
            reinterpret_cast<float4*>(od)[lane] =
                make_float4(acc[0], acc[1], acc[2], acc[3]);
        } else {
            reinterpret_cast<float2*>(od)[lane] = make_float2(acc[0], acc[1]);
        }
    }

#pragma unroll
    for (int j = 0; j < VPL; j++)
        atomicAdd(&scol[lane * VPL + j], csum[j]);
    __syncthreads();
    if (tid < F) atomicAdd(&colsum[tid], scol[tid]);
}

__global__ void zero_colsum_kernel(float* __restrict__ colsum, int F) {
    if (threadIdx.x < F) colsum[threadIdx.x] = 0.0f;
}

// ---------------- PairNorm (PN-SI) -------------------------------------------
template <int PER>
__global__ __launch_bounds__(256)
void pairnorm_kernel(float* __restrict__ X, const float* __restrict__ colsum,
                     int N, int F) {
    int warp = (blockIdx.x * blockDim.x + threadIdx.x) >> 5;
    int lane = threadIdx.x & 31;
    if (warp >= N) return;
    float* xr = X + (long)warp * F;
    const float inv_n = 1.0f / (float)N_NODES;
    float vals[PER];
    float sumsq = 0.0f;
#pragma unroll
    for (int j = 0; j < PER; j++) {
        int f = lane + j * 32;
        float m = colsum[f] * inv_n;
        float v = xr[f] - m;
        vals[j] = v;
        sumsq = fmaf(v, v, sumsq);
    }
#pragma unroll
    for (int o = 16; o > 0; o >>= 1)
        sumsq += __shfl_xor_sync(0xffffffffu, sumsq, o);
    float inv = rsqrtf(1e-6f + sumsq);
#pragma unroll
    for (int j = 0; j < PER; j++)
        xr[lane + j * 32] = vals[j] * inv;
}

// ---------------- decode ------------------------------------------------------
__global__ __launch_bounds__(128)
void decode_kernel(const float* __restrict__ X, const int* __restrict__ pos,
                   const int* __restrict__ neg, float* __restrict__ out) {
    int warp = (blockIdx.x * blockDim.x + threadIdx.x) >> 5;
    int lane = threadIdx.x & 31;
    if (warp >= N_EDGES) return;
    const int* e = (warp < N_POS) ? (pos + 2 * warp) : (neg + 2 * (warp - N_POS));
    int a = e[0];
    int bnode = e[1];
    const float* xa = X + (long)a * F_OUT;
    const float* xb = X + (long)bnode * F_OUT;
    float s = xa[lane] * xb[lane] + xa[lane + 32] * xb[lane + 32];
#pragma unroll
    for (int o = 16; o > 0; o >>= 1)
        s += __shfl_xor_sync(0xffffffffu, s, o);
    if (lane == 0) out[warp] = 1.0f / (1.0f + expf(-s));
}

// ---------------- host orchestration -----------------------------------------
static void run_layer(const float* x_in, int K, const float* W, const float* b,
                      int M, float* support, float* x_out, float* colsum,
                      const int* row_ptr, const int* csr_col, const float* csr_val) {
    int gBlocks = (N_NODES + 127) / 128;
    if (M == 128)
        f16_gemm_kernel<128><<<gBlocks, 256>>>(x_in, W, support, N_NODES, K);
    else
        f16_gemm_kernel<64><<<gBlocks, 256>>>(x_in, W, support, N_NODES, K);

    zero_colsum_kernel<<<1, 128>>>(colsum, M);

    int aggBlocks = N_NODES / 32;   // 3125
    if (M == 128)
        csr_agg_kernel<128, 4><<<aggBlocks, 256>>>(row_ptr, csr_col, csr_val,
                                                   support, b, x_out, colsum);
    else
        csr_agg_kernel<64, 2><<<aggBlocks, 256>>>(row_ptr, csr_col, csr_val,
                                                  support, b, x_out, colsum);

    int pnBlocks = (N_NODES * 32 + 255) / 256;
    if (M == 128)
        pairnorm_kernel<4><<<pnBlocks, 256>>>(x_out, colsum, N_NODES, M);
    else
        pairnorm_kernel<2><<<pnBlocks, 256>>>(x_out, colsum, N_NODES, M);
}

extern "C" void kernel_launch(void* const* d_in, const int* in_sizes, int n_in,
                              void* d_out, int out_size) {
    const float* in_feature = (const float*)d_in[0];
    const int*   adj_row    = (const int*)d_in[1];
    const int*   adj_col    = (const int*)d_in[2];
    const float* adj_val    = (const float*)d_in[3];
    const int*   pos_edge   = (const int*)d_in[4];
    const int*   neg_edge   = (const int*)d_in[5];
    const float* W0 = (const float*)d_in[6];
    const float* b0 = (const float*)d_in[7];
    const float* W1 = (const float*)d_in[8];
    const float* b1 = (const float*)d_in[9];
    const float* W2 = (const float*)d_in[10];
    const float* b2 = (const float*)d_in[11];
    float* out = (float*)d_out;

    float *support, *x, *colsum, *csr_val;
    int *row_ptr, *row_work, *csr_col, *blocksum;
    cudaGetSymbolAddress((void**)&support,  g_support);
    cudaGetSymbolAddress((void**)&x,        g_x);
    cudaGetSymbolAddress((void**)&colsum,   g_colsum);
    cudaGetSymbolAddress((void**)&row_ptr,  g_row_ptr);
    cudaGetSymbolAddress((void**)&row_work, g_row_work);
    cudaGetSymbolAddress((void**)&csr_col,  g_csr_col);
    cudaGetSymbolAddress((void**)&csr_val,  g_csr_val);
    cudaGetSymbolAddress((void**)&blocksum, g_blocksum);

    // ---- build CSR (once; reused by all 3 layers) ----
    hist_zero_kernel<<<(N_NODES + 1 + 255) / 256, 256>>>(row_ptr);
    hist_kernel<<<(N_NNZ + 255) / 256, 256>>>(adj_row, row_ptr);
    scan_a_kernel<<<SCAN_NB, SCAN_BS>>>(row_ptr, blocksum, N_NODES + 1);
    scan_b_kernel<<<1, SCAN_BS>>>(blocksum, SCAN_NB);
    scan_c_kernel<<<SCAN_NB, SCAN_BS>>>(row_ptr, blocksum, row_work, N_NODES + 1);
    scatter_kernel<<<(N_NNZ + 255) / 256, 256>>>(adj_row, adj_col, adj_val,
                                                 row_work, csr_col, csr_val);

    // ---- 3 GCN layers ----
    run_layer(in_feature, F_IN, W0, b0, F_HID, support, x, colsum,
              row_ptr, csr_col, csr_val);
    run_layer(x, F_HID, W1, b1, F_HID, support, x, colsum,
              row_ptr, csr_col, csr_val);
    run_layer(x, F_HID, W2, b2, F_OUT, support, x, colsum,
              row_ptr, csr_col, csr_val);

    // ---- decode ----
    decode_kernel<<<(N_EDGES * 32 + 127) / 128, 128>>>(x, pos_edge, neg_edge, out);
}

// round 13
// speedup vs baseline: 3.9128x; 1.0680x over previous
#include <cuda_runtime.h>
#include <cuda_fp16.h>
#include <math.h>
#include <stdint.h>

#define N_NODES 100000
#define N_NNZ   1000000
#define F_IN    1433
#define F_HID   128
#define F_OUT   64
#define N_POS   20000
#define N_EDGES 40000

#define SCAN_BS 1024
#define SCAN_NB ((N_NODES + 1 + SCAN_BS - 1) / SCAN_BS)   // 98

// ---------------- scratch (static device globals; no allocation) -------------
__device__ __half g_support[(size_t)N_NODES * F_HID];
__device__ float  g_x[(size_t)N_NODES * F_HID];
__device__ float  g_colsum[3][F_HID];
__device__ int    g_row_ptr[N_NODES + 1];
__device__ int    g_row_work[N_NODES + 1];
__device__ int    g_csr_col[N_NNZ];
__device__ float  g_csr_val[N_NNZ];
__device__ int    g_blocksum[SCAN_NB];

// ================= helpers ===================================================
__device__ __forceinline__ uint32_t smem_u32(const void* p) {
    uint32_t a;
    asm("{ .reg .u64 t; cvta.to.shared.u64 t, %1; cvt.u32.u64 %0, t; }"
        : "=r"(a) : "l"(p));
    return a;
}

__device__ __forceinline__ uint32_t pack_f16x2(float f_up, float f_lo) {
    uint32_t r;
    asm("cvt.rn.f16x2.f32 %0, %1, %2;" : "=r"(r) : "f"(f_up), "f"(f_lo));
    return r;
}

#define MMA_F16(d, A0, A1, A2, A3, B0, B1)                                      \
    asm volatile(                                                               \
        "mma.sync.aligned.m16n8k16.row.col.f32.f16.f16.f32 "                    \
        "{%0,%1,%2,%3}, {%4,%5,%6,%7}, {%8,%9}, {%0,%1,%2,%3};"                 \
        : "+f"((d)[0]), "+f"((d)[1]), "+f"((d)[2]), "+f"((d)[3])                \
        : "r"(A0), "r"(A1), "r"(A2), "r"(A3), "r"(B0), "r"(B1));

#define LDMATRIX_X4(r0, r1, r2, r3, addr)                                       \
    asm volatile(                                                               \
        "ldmatrix.sync.aligned.m8n8.x4.shared.b16 {%0,%1,%2,%3}, [%4];"         \
        : "=r"(r0), "=r"(r1), "=r"(r2), "=r"(r3) : "r"(addr));

// ================= fp16 1-term tensor-core GEMM ==============================
// C[Nrows, NC] (fp16) = A[Nrows, K] (fp32) @ W[K, NC] (fp32), computed in fp16.
#define A_STRIDE 80

template <int NC>
__global__ __launch_bounds__(256)
void f16_gemm_kernel(const float* __restrict__ A, const float* __restrict__ B,
                     __half* __restrict__ C, int Nrows, int K) {
    constexpr int NI = NC / 16;
    constexpr int SB = NC + 8;
    constexpr int BITERS = (16 * (NC / 4)) / 256;

    __shared__ __align__(16) uint8_t As[128 * A_STRIDE];
    __shared__ uint32_t Bs[16][SB];

    const int tid  = threadIdx.x;
    const int wid  = tid >> 5;
    const int lane = tid & 31;
    const int g    = lane >> 2;
    const int tg   = lane & 3;
    const int wr   = (wid & 3) * 32;
    const int wc   = (wid >> 2) * (NC / 2);
    const int rowBase = blockIdx.x * 128;

    const uint32_t asBase = smem_u32(As);

    float acc[2][NI][4];
#pragma unroll
    for (int mi = 0; mi < 2; mi++)
#pragma unroll
        for (int ni = 0; ni < NI; ni++)
#pragma unroll
            for (int r = 0; r < 4; r++) acc[mi][ni][r] = 0.0f;

    const int aRow0 = wid * 16;
    float fa[16];

    auto load_A = [&](int kt) {
        const int kglob = kt * 32 + lane;
        const bool kOK = kglob < K;
#pragma unroll
        for (int i = 0; i < 16; i++) {
            const int gr = rowBase + aRow0 + i;
            fa[i] = (kOK && gr < Nrows) ? A[(size_t)gr * K + kglob] : 0.0f;
        }
    };

    auto store_A = [&]() {
#pragma unroll
        for (int i = 0; i < 16; i++) {
            const uint32_t addr = asBase + (aRow0 + i) * A_STRIDE + lane * 2;
            const __half h = __float2half_rn(fa[i]);
            const unsigned short hu = *reinterpret_cast<const unsigned short*>(&h);
            asm volatile("st.shared.b16 [%0], %1;" :: "r"(addr), "h"(hu) : "memory");
        }
    };

    const int lmRow = lane & 15;
    const int lmKoff = (lane >> 4) * 16;

    const int KT = (K + 31) / 32;
    load_A(0);

    for (int kt = 0; kt < KT; kt++) {
        store_A();

#pragma unroll
        for (int it = 0; it < BITERS; it++) {
            const int slot = tid + it * 256;
            const int kp = slot / (NC / 4);
            const int n4 = slot % (NC / 4);
            const int kg0 = kt * 32 + 2 * kp;
            float4 v0 = make_float4(0.f, 0.f, 0.f, 0.f);
            float4 v1 = make_float4(0.f, 0.f, 0.f, 0.f);
            if (kg0 < K)
                v0 = *reinterpret_cast<const float4*>(B + (size_t)kg0 * NC + n4 * 4);
            if (kg0 + 1 < K)
                v1 = *reinterpret_cast<const float4*>(B + (size_t)(kg0 + 1) * NC + n4 * 4);
            Bs[kp][n4 * 4 + 0] = pack_f16x2(v1.x, v0.x);
            Bs[kp][n4 * 4 + 1] = pack_f16x2(v1.y, v0.y);
            Bs[kp][n4 * 4 + 2] = pack_f16x2(v1.z, v0.z);
            Bs[kp][n4 * 4 + 3] = pack_f16x2(v1.w, v0.w);
        }
        __syncthreads();

        if (kt + 1 < KT) load_A(kt + 1);

#pragma unroll
        for (int ks = 0; ks < 2; ks++) {
            uint32_t a[2][4];
#pragma unroll
            for (int mi = 0; mi < 2; mi++) {
                const uint32_t addr = asBase +
                    (wr + mi * 16 + lmRow) * A_STRIDE + ks * 32 + lmKoff;
                LDMATRIX_X4(a[mi][0], a[mi][1], a[mi][2], a[mi][3], addr);
            }
#pragma unroll
            for (int ni = 0; ni < NI; ni++) {
                const int col = wc + ni * 8 + g;
                const uint32_t b0 = Bs[ks * 8 + tg][col];
                const uint32_t b1 = Bs[ks * 8 + tg + 4][col];
#pragma unroll
                for (int mi = 0; mi < 2; mi++) {
                    MMA_F16(acc[mi][ni], a[mi][0], a[mi][1], a[mi][2], a[mi][3],
                            b0, b1);
                }
            }
        }
        __syncthreads();
    }

    // ---- store C as packed fp16 pairs ----
#pragma unroll
    for (int mi = 0; mi < 2; mi++) {
#pragma unroll
        for (int ni = 0; ni < NI; ni++) {
            const int col = wc + ni * 8 + tg * 2;
            const int r0  = rowBase + wr + mi * 16 + g;
            if (r0 < Nrows) {
                uint32_t pk = pack_f16x2(acc[mi][ni][1], acc[mi][ni][0]);
                *reinterpret_cast<uint32_t*>(C + (size_t)r0 * NC + col) = pk;
            }
            if (r0 + 8 < Nrows) {
                uint32_t pk = pack_f16x2(acc[mi][ni][3], acc[mi][ni][2]);
                *reinterpret_cast<uint32_t*>(C + (size_t)(r0 + 8) * NC + col) = pk;
            }
        }
    }
}

// ================= CSR build ==================================================
__global__ void hist_zero_kernel(int* __restrict__ row_ptr, float* __restrict__ colsum) {
    int i = blockIdx.x * blockDim.x + threadIdx.x;
    if (i <= N_NODES) row_ptr[i] = 0;
    if (i < 3 * F_HID) colsum[i] = 0.0f;
}

__global__ void hist_kernel(const int* __restrict__ row, int* __restrict__ row_ptr) {
    int i = blockIdx.x * blockDim.x + threadIdx.x;
    if (i < N_NNZ) atomicAdd(&row_ptr[row[i] + 1], 1);
}

__global__ __launch_bounds__(SCAN_BS)
void scan_a_kernel(int* __restrict__ data, int* __restrict__ blocksum, int n) {
    __shared__ int sh[SCAN_BS];
    int gid = blockIdx.x * SCAN_BS + threadIdx.x;
    int v = (gid < n) ? data[gid] : 0;
    sh[threadIdx.x] = v;
    __syncthreads();
#pragma unroll
    for (int o = 1; o < SCAN_BS; o <<= 1) {
        int t = (threadIdx.x >= o) ? sh[threadIdx.x - o] : 0;
        __syncthreads();
        sh[threadIdx.x] += t;
        __syncthreads();
    }
    if (gid < n) data[gid] = sh[threadIdx.x];
    if (threadIdx.x == SCAN_BS - 1) blocksum[blockIdx.x] = sh[threadIdx.x];
}

__global__ __launch_bounds__(SCAN_BS)
void scan_b_kernel(int* __restrict__ blocksum, int nb) {
    __shared__ int sh[SCAN_BS];
    int v = (threadIdx.x < nb) ? blocksum[threadIdx.x] : 0;
    sh[threadIdx.x] = v;
    __syncthreads();
#pragma unroll
    for (int o = 1; o < SCAN_BS; o <<= 1) {
        int t = (threadIdx.x >= o) ? sh[threadIdx.x - o] : 0;
        __syncthreads();
        sh[threadIdx.x] += t;
        __syncthreads();
    }
    if (threadIdx.x < nb) blocksum[threadIdx.x] = sh[threadIdx.x];
}

__global__ __launch_bounds__(SCAN_BS)
void scan_c_kernel(int* __restrict__ data, const int* __restrict__ blocksum,
                   int* __restrict__ work, int n) {
    int gid = blockIdx.x * SCAN_BS + threadIdx.x;
    if (gid >= n) return;
    int v = data[gid];
    if (blockIdx.x > 0) v += blocksum[blockIdx.x - 1];
    data[gid] = v;
    work[gid] = v;
}

__global__ void scatter_kernel(const int* __restrict__ row, const int* __restrict__ col,
                               const float* __restrict__ val,
                               int* __restrict__ work,
                               int* __restrict__ csr_col, float* __restrict__ csr_val) {
    int i = blockIdx.x * blockDim.x + threadIdx.x;
    if (i >= N_NNZ) return;
    int pos = atomicAdd(&work[row[i]], 1);
    csr_col[pos] = col[i];
    csr_val[pos] = val[i];
}

// ================= fused CSR aggregation (fp16 gather) =======================
template <int F, int VPL>
__global__ __launch_bounds__(256)
void csr_agg_kernel(const int* __restrict__ row_ptr,
                    const int* __restrict__ csr_col,
                    const float* __restrict__ csr_val,
                    const __half* __restrict__ X,
                    const float* __restrict__ bias,
                    float* __restrict__ Xout,
                    float* __restrict__ colsum) {
    __shared__ float scol[F];
    const int tid  = threadIdx.x;
    const int wid  = tid >> 5;
    const int lane = tid & 31;

    if (tid < F) scol[tid] = 0.0f;
    __syncthreads();

    float bz[VPL];
#pragma unroll
    for (int j = 0; j < VPL; j++) bz[j] = bias[lane * VPL + j];

    float csum[VPL];
#pragma unroll
    for (int j = 0; j < VPL; j++) csum[j] = 0.0f;

    const int rowBase = blockIdx.x * 32 + wid * 4;

#pragma unroll
    for (int rr = 0; rr < 4; rr++) {
        const int r = rowBase + rr;
        const int start = row_ptr[r];
        const int end   = row_ptr[r + 1];

        float acc[VPL];
#pragma unroll
        for (int j = 0; j < VPL; j++) acc[j] = 0.0f;

        for (int base = start; base < end; base += 32) {
            int idx = base + lane;
            int   cv = 0;
            float vv = 0.0f;
            if (idx < end) { cv = csr_col[idx]; vv = csr_val[idx]; }
            int count = min(32, end - base);
            for (int j = 0; j < count; j++) {
                int   c = __shfl_sync(0xffffffffu, cv, j);
                float v = __shfl_sync(0xffffffffu, vv, j);
                if (VPL == 4) {
                    const uint2* xr = reinterpret_cast<const uint2*>(X + (size_t)c * F);
                    uint2 u = xr[lane];
                    float2 f0 = __half22float2(*reinterpret_cast<__half2*>(&u.x));
                    float2 f1 = __half22float2(*reinterpret_cast<__half2*>(&u.y));
                    acc[0] = fmaf(v, f0.x, acc[0]);
                    acc[1] = fmaf(v, f0.y, acc[1]);
                    acc[2] = fmaf(v, f1.x, acc[2]);
                    acc[3] = fmaf(v, f1.y, acc[3]);
                } else {
                    const uint32_t* xr = reinterpret_cast<const uint32_t*>(X + (size_t)c * F);
                    uint32_t u = xr[lane];
                    float2 f0 = __half22float2(*reinterpret_cast<__half2*>(&u));
                    acc[0] = fmaf(v, f0.x, acc[0]);
                    acc[1] = fmaf(v, f0.y, acc[1]);
                }
            }
        }

#pragma unroll
        for (int j = 0; j < VPL; j++) {
            float o = fmaxf(acc[j] + bz[j], 0.0f);
            acc[j] = o;
            csum[j] += o;
        }
        float* od = Xout + (size_t)r * F;
        if (VPL == 4) {
            reinterpret_cast<float4*>(od)[lane] =
                make_float4(acc[0], acc[1], acc[2], acc[3]);
        } else {
            reinterpret_cast<float2*>(od)[lane] = make_float2(acc[0], acc[1]);
        }
    }

#pragma unroll
    for (int j = 0; j < VPL; j++)
        atomicAdd(&scol[lane * VPL + j], csum[j]);
    __syncthreads();
    if (tid < F) atomicAdd(&colsum[tid], scol[tid]);
}

// ---------------- PairNorm (PN-SI) -------------------------------------------
template <int PER>
__global__ __launch_bounds__(256)
void pairnorm_kernel(float* __restrict__ X, const float* __restrict__ colsum,
                     int N, int F) {
    int warp = (blockIdx.x * blockDim.x + threadIdx.x) >> 5;
    int lane = threadIdx.x & 31;
    if (warp >= N) return;
    float* xr = X + (long)warp * F;
    const float inv_n = 1.0f / (float)N_NODES;
    float vals[PER];
    float sumsq = 0.0f;
#pragma unroll
    for (int j = 0; j < PER; j++) {
        int f = lane + j * 32;
        float m = colsum[f] * inv_n;
        float v = xr[f] - m;
        vals[j] = v;
        sumsq = fmaf(v, v, sumsq);
    }
#pragma unroll
    for (int o = 16; o > 0; o >>= 1)
        sumsq += __shfl_xor_sync(0xffffffffu, sumsq, o);
    float inv = rsqrtf(1e-6f + sumsq);
#pragma unroll
    for (int j = 0; j < PER; j++)
        xr[lane + j * 32] = vals[j] * inv;
}

// ---------------- decode ------------------------------------------------------
__global__ __launch_bounds__(128)
void decode_kernel(const float* __restrict__ X, const int* __restrict__ pos,
                   const int* __restrict__ neg, float* __restrict__ out) {
    int warp = (blockIdx.x * blockDim.x + threadIdx.x) >> 5;
    int lane = threadIdx.x & 31;
    if (warp >= N_EDGES) return;
    const int* e = (warp < N_POS) ? (pos + 2 * warp) : (neg + 2 * (warp - N_POS));
    int a = e[0];
    int bnode = e[1];
    const float* xa = X + (long)a * F_OUT;
    const float* xb = X + (long)bnode * F_OUT;
    float s = xa[lane] * xb[lane] + xa[lane + 32] * xb[lane + 32];
#pragma unroll
    for (int o = 16; o > 0; o >>= 1)
        s += __shfl_xor_sync(0xffffffffu, s, o);
    if (lane == 0) out[warp] = 1.0f / (1.0f + expf(-s));
}

// ---------------- host orchestration -----------------------------------------
static void run_layer(const float* x_in, int K, const float* W, const float* b,
                      int M, __half* support, float* x_out, float* colsum,
                      const int* row_ptr, const int* csr_col, const float* csr_val) {
    int gBlocks = (N_NODES + 127) / 128;
    if (M == 128)
        f16_gemm_kernel<128><<<gBlocks, 256>>>(x_in, W, support, N_NODES, K);
    else
        f16_gemm_kernel<64><<<gBlocks, 256>>>(x_in, W, support, N_NODES, K);

    int aggBlocks = N_NODES / 32;   // 3125
    if (M == 128)
        csr_agg_kernel<128, 4><<<aggBlocks, 256>>>(row_ptr, csr_col, csr_val,
                                                   support, b, x_out, colsum);
    else
        csr_agg_kernel<64, 2><<<aggBlocks, 256>>>(row_ptr, csr_col, csr_val,
                                                  support, b, x_out, colsum);

    int pnBlocks = (N_NODES * 32 + 255) / 256;
    if (M == 128)
        pairnorm_kernel<4><<<pnBlocks, 256>>>(x_out, colsum, N_NODES, M);
    else
        pairnorm_kernel<2><<<pnBlocks, 256>>>(x_out, colsum, N_NODES, M);
}

extern "C" void kernel_launch(void* const* d_in, const int* in_sizes, int n_in,
                              void* d_out, int out_size) {
    const float* in_feature = (const float*)d_in[0];
    const int*   adj_row    = (const int*)d_in[1];
    const int*   adj_col    = (const int*)d_in[2];
    const float* adj_val    = (const float*)d_in[3];
    const int*   pos_edge   = (const int*)d_in[4];
    const int*   neg_edge   = (const int*)d_in[5];
    const float* W0 = (const float*)d_in[6];
    const float* b0 = (const float*)d_in[7];
    const float* W1 = (const float*)d_in[8];
    const float* b1 = (const float*)d_in[9];
    const float* W2 = (const float*)d_in[10];
    const float* b2 = (const float*)d_in[11];
    float* out = (float*)d_out;

    __half* support;
    float *x, *colsum, *csr_val;
    int *row_ptr, *row_work, *csr_col, *blocksum;
    cudaGetSymbolAddress((void**)&support,  g_support);
    cudaGetSymbolAddress((void**)&x,        g_x);
    cudaGetSymbolAddress((void**)&colsum,   g_colsum);
    cudaGetSymbolAddress((void**)&row_ptr,  g_row_ptr);
    cudaGetSymbolAddress((void**)&row_work, g_row_work);
    cudaGetSymbolAddress((void**)&csr_col,  g_csr_col);
    cudaGetSymbolAddress((void**)&csr_val,  g_csr_val);
    cudaGetSymbolAddress((void**)&blocksum, g_blocksum);

    // ---- build CSR (once; reused by all 3 layers); also zero colsums ----
    hist_zero_kernel<<<(N_NODES + 1 + 255) / 256, 256>>>(row_ptr, colsum);
    hist_kernel<<<(N_NNZ + 255) / 256, 256>>>(adj_row, row_ptr);
    scan_a_kernel<<<SCAN_NB, SCAN_BS>>>(row_ptr, blocksum, N_NODES + 1);
    scan_b_kernel<<<1, SCAN_BS>>>(blocksum, SCAN_NB);
    scan_c_kernel<<<SCAN_NB, SCAN_BS>>>(row_ptr, blocksum, row_work, N_NODES + 1);
    scatter_kernel<<<(N_NNZ + 255) / 256, 256>>>(adj_row, adj_col, adj_val,
                                                 row_work, csr_col, csr_val);

    // ---- 3 GCN layers ----
    run_layer(in_feature, F_IN, W0, b0, F_HID, support, x, colsum + 0 * F_HID,
              row_ptr, csr_col, csr_val);
    run_layer(x, F_HID, W1, b1, F_HID, support, x, colsum + 1 * F_HID,
              row_ptr, csr_col, csr_val);
    run_layer(x, F_HID, W2, b2, F_OUT, support, x, colsum + 2 * F_HID,
              row_ptr, csr_col, csr_val);

    // ---- decode ----
    decode_kernel<<<(N_EDGES * 32 + 127) / 128, 128>>>(x, pos_edge, neg_edge, out);
}